// round 1
// baseline (speedup 1.0000x reference)
#include <cuda_runtime.h>
#include <math.h>

typedef long long ll;

#define NT 768
#define CA 768
#define CS 384
#define CZ 128
#define NH 16
#define CH 48
#define NN (768*768)

// ---------------- scratch (device globals; no allocation allowed) ----------------
__device__ float g_slnA[NT*CS], g_slnT[NT*CS];
__device__ float g_gateA[NT*CA], g_skipA[NT*CA], g_outGA[NT*CA];
__device__ float g_gateT[NT*CA], g_skipT[NT*CA], g_outGT[NT*CA];
__device__ float g_aln[NT*CA];
__device__ float g_q[NT*CA], g_kT[NT*CA], g_v[NT*CA], g_g[NT*CA];
__device__ float g_logits[NH*NN];
__device__ float g_og[NT*CA];
__device__ float g_anew[NT*CA];
__device__ float g_h1[NT*1536], g_hid[NT*1536];
__device__ float g_Wp[NH*CZ], g_Sv[NH], g_Cv[NH], g_maskb[NT], g_maskf[NT];

// ---------------- helpers ----------------
__device__ __forceinline__ float blkreduce(float v, bool domax) {
    __shared__ float sm[32];
    const unsigned F = 0xffffffffu;
    #pragma unroll
    for (int o = 16; o; o >>= 1) {
        float u = __shfl_xor_sync(F, v, o);
        v = domax ? fmaxf(v, u) : v + u;
    }
    __syncthreads();
    if ((threadIdx.x & 31) == 0) sm[threadIdx.x >> 5] = v;
    __syncthreads();
    int nw = blockDim.x >> 5;
    if (threadIdx.x < 32) {
        float u = (threadIdx.x < nw) ? sm[threadIdx.x] : (domax ? -3.4e38f : 0.f);
        #pragma unroll
        for (int o = 16; o; o >>= 1) {
            float w = __shfl_xor_sync(F, u, o);
            u = domax ? fmaxf(u, w) : u + w;
        }
        if (threadIdx.x == 0) sm[0] = u;
    }
    __syncthreads();
    return sm[0];
}

// ---------------- prep: mask vectors + folded pair-bias weights ----------------
__global__ void prep_k(const int* __restrict__ mask, const float* __restrict__ zg,
                       const float* __restrict__ zb, const float* __restrict__ wb) {
    int t = threadIdx.x;
    for (int i = t; i < NT; i += 256) {
        float m = (float)mask[i];
        g_maskf[i] = m;
        g_maskb[i] = (m - 1.f) * 1e9f;
    }
    for (int i = t; i < NH*CZ; i += 256) {
        int h = i >> 7, c = i & 127;
        g_Wp[i] = zg[c] * wb[c*NH + h];
    }
    if (t < NH) {
        float s = 0.f, cs = 0.f;
        for (int c = 0; c < CZ; c++) {
            s  += zg[c] * wb[c*NH + t];
            cs += zb[c] * wb[c*NH + t];
        }
        g_Sv[t] = s; g_Cv[t] = cs;
    }
}

// ---------------- LN(s) with two scale vectors ----------------
__global__ __launch_bounds__(128) void lns_k(const float* __restrict__ s,
                                             const float* __restrict__ gA,
                                             const float* __restrict__ gT,
                                             float* __restrict__ oA, float* __restrict__ oT) {
    int r = blockIdx.x, t = threadIdx.x;
    const float* x = s + (ll)r * CS;
    float v[3]; float su = 0.f, q = 0.f;
    #pragma unroll
    for (int i = 0; i < 3; i++) { v[i] = x[t + 128*i]; su += v[i]; q += v[i]*v[i]; }
    su = blkreduce(su, false);
    q  = blkreduce(q, false);
    float mu = su * (1.f/CS);
    float rs = rsqrtf(q * (1.f/CS) - mu*mu + 1e-5f);
    ll base = (ll)r * CS;
    #pragma unroll
    for (int i = 0; i < 3; i++) {
        int c = t + 128*i;
        float xh = (v[i] - mu) * rs;
        oA[base + c] = xh * gA[c];
        oT[base + c] = xh * gT[c];
    }
}

// ---------------- AdaLN combine: out = gate * LN(a) + skip ----------------
__global__ __launch_bounds__(256) void adaln_k(const float* __restrict__ a,
                                               const float* __restrict__ gate,
                                               const float* __restrict__ skip,
                                               float* __restrict__ out) {
    int r = blockIdx.x, t = threadIdx.x;
    const float* x = a + (ll)r * CA;
    float v[3]; float su = 0.f, q = 0.f;
    #pragma unroll
    for (int i = 0; i < 3; i++) { v[i] = x[t + 256*i]; su += v[i]; q += v[i]*v[i]; }
    su = blkreduce(su, false);
    q  = blkreduce(q, false);
    float mu = su * (1.f/CA);
    float rs = rsqrtf(q * (1.f/CA) - mu*mu + 1e-5f);
    ll base = (ll)r * CA;
    #pragma unroll
    for (int i = 0; i < 3; i++) {
        int c = t + 256*i;
        out[base + c] = gate[base + c] * ((v[i] - mu) * rs) + skip[base + c];
    }
}

// ---------------- pair bias: LN(z)*g+b @ wb, algebraically folded ----------------
// bias_h = rs*(dot(z, Wp_h) - mu*S_h) + C_h ; output layout [h][q][k]
__global__ __launch_bounds__(256) void pairbias_k(const float* __restrict__ z,
                                                  float* __restrict__ out) {
    __shared__ float Wp[NH][CZ];
    __shared__ float Sv[NH], Cv[NH];
    __shared__ float stage[NH][8];
    int t = threadIdx.x;
    for (int i = t; i < NH*CZ; i += 256) ((float*)Wp)[i] = g_Wp[i];
    if (t < NH) { Sv[t] = g_Sv[t]; Cv[t] = g_Cv[t]; }
    __syncthreads();
    int w = t >> 5, l = t & 31;
    int p = blockIdx.x * 8 + w;
    const float4 zv = *(const float4*)(z + (ll)p * CZ + 4*l);
    float su = zv.x + zv.y + zv.z + zv.w;
    float sq = zv.x*zv.x + zv.y*zv.y + zv.z*zv.z + zv.w*zv.w;
    const unsigned F = 0xffffffffu;
    #pragma unroll
    for (int o = 16; o; o >>= 1) {
        su += __shfl_xor_sync(F, su, o);
        sq += __shfl_xor_sync(F, sq, o);
    }
    float mu = su * (1.f/CZ);
    float rs = rsqrtf(sq * (1.f/CZ) - mu*mu + 1e-5f);
    float part[NH];
    #pragma unroll
    for (int h = 0; h < NH; h++) {
        float4 wv = *(const float4*)&Wp[h][4*l];
        part[h] = zv.x*wv.x + zv.y*wv.y + zv.z*wv.z + zv.w*wv.w;
    }
    #pragma unroll
    for (int o = 16; o; o >>= 1)
        #pragma unroll
        for (int h = 0; h < NH; h++)
            part[h] += __shfl_xor_sync(F, part[h], o);
    if (l < NH) stage[l][w] = rs * (part[l] - mu * Sv[l]) + Cv[l];
    __syncthreads();
    if (t < 128) {
        int h = t >> 3, j = t & 7;
        out[(ll)h * NN + (ll)blockIdx.x * 8 + j] = stage[h][j];
    }
}

// ---------------- softmax over last dim (rows of 768) ----------------
__global__ __launch_bounds__(256) void softmax_k(float* __restrict__ p) {
    float* x = p + (ll)blockIdx.x * NT;
    int t = threadIdx.x;
    float v0 = x[t], v1 = x[t+256], v2 = x[t+512];
    float mx = blkreduce(fmaxf(v0, fmaxf(v1, v2)), true);
    float e0 = __expf(v0 - mx), e1 = __expf(v1 - mx), e2 = __expf(v2 - mx);
    float s = blkreduce(e0 + e1 + e2, false);
    float inv = 1.f / s;
    x[t] = e0*inv; x[t+256] = e1*inv; x[t+512] = e2*inv;
}

// ---------------- generic tiled SGEMM with fused epilogue ----------------
// FLG bits: 1=BVEC 2=MATB 4=MUL 8=ADD 16=ROWSCALE 32=STORE_TRANSPOSED
template<int ACT, int FLG>
__global__ __launch_bounds__(256) void sgemm_k(
    const float* __restrict__ A, int lda, ll sA,
    const float* __restrict__ W, int ldw, ll sW,
    float* __restrict__ C, int ldc, ll sC,
    const float* __restrict__ bvec,
    const float* __restrict__ matb, ll sMB, int ldmb,
    const float* __restrict__ mul, ll sMul, int ldmul,
    const float* __restrict__ addm, int ldadd,
    const float* __restrict__ rowsc,
    int N, int K, float scale)
{
    constexpr bool BVEC = FLG & 1, MATB = FLG & 2, MULF = FLG & 4,
                   ADDF = FLG & 8, ROWS = FLG & 16, STORET = FLG & 32;
    int z = blockIdx.z;
    A += z * sA; W += z * sW; C += z * sC;
    const float* mb = MATB ? matb + z * sMB : nullptr;
    const float* ml = MULF ? mul + z * sMul : nullptr;

    __shared__ float As[16][65];
    __shared__ float Ws[16][64];
    int t = threadIdx.x;
    int tx = t & 15, ty = t >> 4;
    int m0 = blockIdx.y * 64, n0 = blockIdx.x * 64;
    float acc[4][4] = {};
    int ar = t >> 2, ac = (t & 3) * 4;
    int wr = t >> 4, wc = (t & 15) * 4;
    bool nfull = (n0 + 64 <= N);
    for (int k0 = 0; k0 < K; k0 += 16) {
        float4 av = *(const float4*)&A[(ll)(m0 + ar) * lda + k0 + ac];
        As[ac+0][ar] = av.x; As[ac+1][ar] = av.y;
        As[ac+2][ar] = av.z; As[ac+3][ar] = av.w;
        if (nfull) {
            *(float4*)&Ws[wr][wc] = *(const float4*)&W[(ll)(k0 + wr) * ldw + n0 + wc];
        } else {
            #pragma unroll
            for (int i = 0; i < 4; i++)
                Ws[wr][wc+i] = (n0 + wc + i < N) ? W[(ll)(k0 + wr) * ldw + n0 + wc + i] : 0.f;
        }
        __syncthreads();
        #pragma unroll
        for (int kk = 0; kk < 16; kk++) {
            float af[4], wf[4];
            #pragma unroll
            for (int i = 0; i < 4; i++) af[i] = As[kk][ty + 16*i];
            #pragma unroll
            for (int j = 0; j < 4; j++) wf[j] = Ws[kk][tx + 16*j];
            #pragma unroll
            for (int i = 0; i < 4; i++)
                #pragma unroll
                for (int j = 0; j < 4; j++)
                    acc[i][j] = fmaf(af[i], wf[j], acc[i][j]);
        }
        __syncthreads();
    }
    #pragma unroll
    for (int i = 0; i < 4; i++) {
        int m = m0 + ty + 16*i;
        #pragma unroll
        for (int j = 0; j < 4; j++) {
            int n = n0 + tx + 16*j;
            if (n >= N) continue;
            float v = acc[i][j] * scale;
            if (BVEC) v += bvec[n];
            if (MATB) v += mb[(ll)m * ldmb + n];
            if (ACT == 1) v = 1.f / (1.f + __expf(-v));
            else if (ACT == 2) v = v / (1.f + __expf(-v));
            if (MULF) v *= ml[(ll)m * ldmul + n];
            if (ROWS) v *= rowsc[m];
            if (ADDF) v += addm[(ll)m * ldadd + n];
            if (STORET) C[(ll)n * ldc + m] = v;
            else        C[(ll)m * ldc + n] = v;
        }
    }
}

// ---------------- host orchestration ----------------
#define SYM(p, name) do { void* _t; cudaGetSymbolAddress(&_t, name); p = (float*)_t; } while (0)
#define NUL ((const float*)nullptr)

extern "C" void kernel_launch(void* const* d_in, const int* in_sizes, int n_in,
                              void* d_out, int out_size) {
    const float* a    = (const float*)d_in[0];
    const float* s    = (const float*)d_in[1];
    const float* z    = (const float*)d_in[2];
    const int*   mask = (const int*)  d_in[3];
    const float* a_slng  = (const float*)d_in[4];
    const float* a_gw    = (const float*)d_in[5];
    const float* a_gb    = (const float*)d_in[6];
    const float* a_sw    = (const float*)d_in[7];
    const float* wq   = (const float*)d_in[8];
    const float* bq   = (const float*)d_in[9];
    const float* wk   = (const float*)d_in[10];
    const float* wv   = (const float*)d_in[11];
    const float* zlng = (const float*)d_in[12];
    const float* zlnb = (const float*)d_in[13];
    const float* wb   = (const float*)d_in[14];
    const float* wg   = (const float*)d_in[15];
    const float* wo   = (const float*)d_in[16];
    const float* aogw = (const float*)d_in[17];
    const float* aogb = (const float*)d_in[18];
    const float* t_slng = (const float*)d_in[19];
    const float* t_gw   = (const float*)d_in[20];
    const float* t_gb   = (const float*)d_in[21];
    const float* t_sw   = (const float*)d_in[22];
    const float* w1   = (const float*)d_in[23];
    const float* w2   = (const float*)d_in[24];
    const float* two  = (const float*)d_in[25];
    const float* togw = (const float*)d_in[26];
    const float* togb = (const float*)d_in[27];
    float* out = (float*)d_out;

    float *slnA,*slnT,*gateA,*skipA,*outGA,*gateT,*skipT,*outGT,*aln;
    float *qb,*kT,*vb,*gb,*logits,*og,*anew,*h1,*hid,*maskb,*maskf;
    SYM(slnA, g_slnA); SYM(slnT, g_slnT);
    SYM(gateA, g_gateA); SYM(skipA, g_skipA); SYM(outGA, g_outGA);
    SYM(gateT, g_gateT); SYM(skipT, g_skipT); SYM(outGT, g_outGT);
    SYM(aln, g_aln);
    SYM(qb, g_q); SYM(kT, g_kT); SYM(vb, g_v); SYM(gb, g_g);
    SYM(logits, g_logits); SYM(og, g_og); SYM(anew, g_anew);
    SYM(h1, g_h1); SYM(hid, g_hid);
    SYM(maskb, g_maskb); SYM(maskf, g_maskf);

    dim3 blk(256);
    dim3 g12(12, 12, 1), g24(24, 12, 1), gH(12, 12, 16), gO(1, 12, 16);

    prep_k<<<1, 256>>>(mask, zlng, zlnb, wb);
    lns_k<<<NT, 128>>>(s, a_slng, t_slng, slnA, slnT);

    // s-conditioned gates / skips (K=384)
    sgemm_k<1,1><<<g12,blk>>>(slnA,CS,0, a_gw,CA,0, gateA,CA,0, a_gb, NUL,0,0, NUL,0,0, NUL,0, NUL, CA,CS,1.f);
    sgemm_k<0,0><<<g12,blk>>>(slnA,CS,0, a_sw,CA,0, skipA,CA,0, NUL, NUL,0,0, NUL,0,0, NUL,0, NUL, CA,CS,1.f);
    sgemm_k<1,1><<<g12,blk>>>(s,   CS,0, aogw,CA,0, outGA,CA,0, aogb, NUL,0,0, NUL,0,0, NUL,0, NUL, CA,CS,1.f);
    sgemm_k<1,1><<<g12,blk>>>(slnT,CS,0, t_gw,CA,0, gateT,CA,0, t_gb, NUL,0,0, NUL,0,0, NUL,0, NUL, CA,CS,1.f);
    sgemm_k<0,0><<<g12,blk>>>(slnT,CS,0, t_sw,CA,0, skipT,CA,0, NUL, NUL,0,0, NUL,0,0, NUL,0, NUL, CA,CS,1.f);
    sgemm_k<1,1><<<g12,blk>>>(s,   CS,0, togw,CA,0, outGT,CA,0, togb, NUL,0,0, NUL,0,0, NUL,0, NUL, CA,CS,1.f);

    // a_ln = gateA * LN(a) + skipA
    adaln_k<<<NT, 256>>>(a, gateA, skipA, aln);

    // projections (K=768): q(+bias), kT(transposed store), v, g(sigmoid)
    sgemm_k<0,1 ><<<g12,blk>>>(aln,CA,0, wq,CA,0, qb,CA,0, bq,  NUL,0,0, NUL,0,0, NUL,0, NUL, CA,CA,1.f);
    sgemm_k<0,32><<<g12,blk>>>(aln,CA,0, wk,CA,0, kT,NT,0, NUL, NUL,0,0, NUL,0,0, NUL,0, NUL, CA,CA,1.f);
    sgemm_k<0,0 ><<<g12,blk>>>(aln,CA,0, wv,CA,0, vb,CA,0, NUL, NUL,0,0, NUL,0,0, NUL,0, NUL, CA,CA,1.f);
    sgemm_k<1,0 ><<<g12,blk>>>(aln,CA,0, wg,CA,0, gb,CA,0, NUL, NUL,0,0, NUL,0,0, NUL,0, NUL, CA,CA,1.f);

    // pair bias -> logits buffer [h][q][k]
    pairbias_k<<<NN/8, 256>>>(z, logits);

    // logits[h] = q_h @ kT_h * (1/sqrt(48)) + bias + maskbias (in place on bias buffer)
    sgemm_k<0,3><<<gH,blk>>>(qb,CA,48, kT,NT,(ll)48*NT, logits,NT,(ll)NN,
                             maskb, logits,(ll)NN,NT, NUL,0,0, NUL,0, NUL,
                             NT, CH, 0.14433756729740643f);

    softmax_k<<<NH*NT, 256>>>(logits);

    // o_h = attn_h @ v_h, epilogue *gate g (per head column slice)
    sgemm_k<0,4><<<gO,blk>>>(logits,NT,(ll)NN, vb,CA,48, og,CA,48,
                             NUL, NUL,0,0, gb,48,CA, NUL,0, NUL,
                             CH, NT, 1.f);

    // a_new = a + outGA * (og @ wo)
    sgemm_k<0,12><<<g12,blk>>>(og,CA,0, wo,CA,0, anew,CA,0,
                               NUL, NUL,0,0, outGA,0,CA, a,CA, NUL,
                               CA, CA, 1.f);

    // t_ln = gateT * LN(a_new) + skipT
    adaln_k<<<NT, 256>>>(anew, gateT, skipT, aln);

    // SwiGLU: h1 = silu(t_ln @ w1); hid = (t_ln @ w2) * h1
    sgemm_k<2,0><<<g24,blk>>>(aln,CA,0, w1,1536,0, h1,1536,0,
                              NUL, NUL,0,0, NUL,0,0, NUL,0, NUL, 1536,CA,1.f);
    sgemm_k<0,4><<<g24,blk>>>(aln,CA,0, w2,1536,0, hid,1536,0,
                              NUL, NUL,0,0, h1,0,1536, NUL,0, NUL, 1536,CA,1.f);

    // out = a_new + maskf * outGT * (hid @ tr_wo)
    sgemm_k<0,28><<<g12,blk>>>(hid,1536,0, two,CA,0, out,CA,0,
                               NUL, NUL,0,0, outGT,0,CA, anew,CA, maskf,
                               CA, 1536, 1.f);
}

// round 2
// speedup vs baseline: 1.4566x; 1.4566x over previous
#include <cuda_runtime.h>
#include <math.h>

typedef long long ll;
typedef unsigned long long ull;

#define NT 768
#define CA 768
#define CS 384
#define CZ 128
#define NH 16
#define CH 48
#define NN (768*768)

// ---------------- scratch ----------------
__device__ float g_slnA[NT*CS], g_slnT[NT*CS];
__device__ float g_gateA[NT*CA], g_skipA[NT*CA], g_outGA[NT*CA];
__device__ float g_gateT[NT*CA], g_skipT[NT*CA], g_outGT[NT*CA];
__device__ float g_aln[NT*CA];
__device__ float g_q[NT*CA], g_kT[NT*CA], g_v[NT*CA], g_g[NT*CA];
__device__ float g_logits[NH*NN];
__device__ float g_og[NT*CA];
__device__ float g_anew[NT*CA];
__device__ float g_h1[NT*1536], g_hid[NT*1536];
__device__ float g_Wp[NH*CZ], g_Sv[NH], g_Cv[NH], g_maskb[NT], g_maskf[NT];

// ---------------- helpers ----------------
__device__ __forceinline__ float t32(float x) {
    unsigned u; asm("cvt.rna.tf32.f32 %0, %1;" : "=r"(u) : "f"(x));
    return __uint_as_float(u);
}
__device__ __forceinline__ ull pk2(float x, float y) {
    ull r; asm("mov.b64 %0, {%1, %2};" : "=l"(r) : "f"(x), "f"(y)); return r;
}
__device__ __forceinline__ void fma2(ull &d, ull a, ull b) {
    asm("fma.rn.f32x2 %0, %1, %2, %0;" : "+l"(d) : "l"(a), "l"(b));
}
__device__ __forceinline__ float sum2(ull v) {
    float x, y; asm("mov.b64 {%0, %1}, %2;" : "=f"(x), "=f"(y) : "l"(v));
    return x + y;
}

__device__ __forceinline__ float blkreduce(float v, bool domax) {
    __shared__ float sm[32];
    const unsigned F = 0xffffffffu;
    #pragma unroll
    for (int o = 16; o; o >>= 1) {
        float u = __shfl_xor_sync(F, v, o);
        v = domax ? fmaxf(v, u) : v + u;
    }
    __syncthreads();
    if ((threadIdx.x & 31) == 0) sm[threadIdx.x >> 5] = v;
    __syncthreads();
    int nw = blockDim.x >> 5;
    if (threadIdx.x < 32) {
        float u = (threadIdx.x < nw) ? sm[threadIdx.x] : (domax ? -3.4e38f : 0.f);
        #pragma unroll
        for (int o = 16; o; o >>= 1) {
            float w = __shfl_xor_sync(F, u, o);
            u = domax ? fmaxf(u, w) : u + w;
        }
        if (threadIdx.x == 0) sm[0] = u;
    }
    __syncthreads();
    return sm[0];
}

// ---------------- prep ----------------
__global__ void prep_k(const int* __restrict__ mask, const float* __restrict__ zg,
                       const float* __restrict__ zb, const float* __restrict__ wb) {
    int t = threadIdx.x;
    for (int i = t; i < NT; i += 256) {
        float m = (float)mask[i];
        g_maskf[i] = m;
        g_maskb[i] = (m - 1.f) * 1e9f;
    }
    for (int i = t; i < NH*CZ; i += 256) {
        int h = i >> 7, c = i & 127;
        g_Wp[i] = zg[c] * wb[c*NH + h];
    }
    if (t < NH) {
        float s = 0.f, cs = 0.f;
        for (int c = 0; c < CZ; c++) {
            s  += zg[c] * wb[c*NH + t];
            cs += zb[c] * wb[c*NH + t];
        }
        g_Sv[t] = s; g_Cv[t] = cs;
    }
}

// ---------------- LN(s) dual scale ----------------
__global__ __launch_bounds__(128) void lns_k(const float* __restrict__ s,
                                             const float* __restrict__ gA,
                                             const float* __restrict__ gT,
                                             float* __restrict__ oA, float* __restrict__ oT) {
    int r = blockIdx.x, t = threadIdx.x;
    const float* x = s + (ll)r * CS;
    float v[3]; float su = 0.f, q = 0.f;
    #pragma unroll
    for (int i = 0; i < 3; i++) { v[i] = x[t + 128*i]; su += v[i]; q += v[i]*v[i]; }
    su = blkreduce(su, false);
    q  = blkreduce(q, false);
    float mu = su * (1.f/CS);
    float rs = rsqrtf(q * (1.f/CS) - mu*mu + 1e-5f);
    ll base = (ll)r * CS;
    #pragma unroll
    for (int i = 0; i < 3; i++) {
        int c = t + 128*i;
        float xh = (v[i] - mu) * rs;
        oA[base + c] = xh * gA[c];
        oT[base + c] = xh * gT[c];
    }
}

// ---------------- AdaLN combine ----------------
__global__ __launch_bounds__(256) void adaln_k(const float* __restrict__ a,
                                               const float* __restrict__ gate,
                                               const float* __restrict__ skip,
                                               float* __restrict__ out) {
    int r = blockIdx.x, t = threadIdx.x;
    const float* x = a + (ll)r * CA;
    float v[3]; float su = 0.f, q = 0.f;
    #pragma unroll
    for (int i = 0; i < 3; i++) { v[i] = x[t + 256*i]; su += v[i]; q += v[i]*v[i]; }
    su = blkreduce(su, false);
    q  = blkreduce(q, false);
    float mu = su * (1.f/CA);
    float rs = rsqrtf(q * (1.f/CA) - mu*mu + 1e-5f);
    ll base = (ll)r * CA;
    #pragma unroll
    for (int i = 0; i < 3; i++) {
        int c = t + 256*i;
        out[base + c] = gate[base + c] * ((v[i] - mu) * rs) + skip[base + c];
    }
}

// ---------------- pair bias (register-W, warp-per-pair, f32x2) ----------------
#define PPW 16
__global__ __launch_bounds__(256) void pairbias_k(const float* __restrict__ z,
                                                  float* __restrict__ out) {
    __shared__ float stage[8][PPW][17];
    int t = threadIdx.x, w = t >> 5, l = t & 31;
    int h = l & 15, half = l >> 4;
    const unsigned F = 0xffffffffu;

    // W in registers: lane holds Wp[h][half*64 .. +63] as 32 packed f32x2
    ull wreg[32];
    {
        const float4* wrow = (const float4*)(&g_Wp[h*CZ + half*64]);
        #pragma unroll
        for (int j = 0; j < 16; j++) {
            float4 wv = wrow[j];
            wreg[2*j]   = pk2(wv.x, wv.y);
            wreg[2*j+1] = pk2(wv.z, wv.w);
        }
    }
    float Svr = g_Sv[h], Cvr = g_Cv[h];
    ll pbase = ((ll)blockIdx.x * 8 + w) * PPW;

    for (int pi = 0; pi < PPW; pi++) {
        ll p = pbase + pi;
        const float4* zr = (const float4*)(z + p * CZ);
        // stats chunk: lane covers 4 distinct elements
        float4 zc = zr[l];
        float su = zc.x + zc.y + zc.z + zc.w;
        float sq = zc.x*zc.x + zc.y*zc.y + zc.z*zc.z + zc.w*zc.w;
        // dot over own half (broadcast loads)
        ull acc = 0;
        const float4* zh = zr + half * 16;
        #pragma unroll
        for (int j = 0; j < 16; j++) {
            float4 zv = zh[j];
            fma2(acc, pk2(zv.x, zv.y), wreg[2*j]);
            fma2(acc, pk2(zv.z, zv.w), wreg[2*j+1]);
        }
        #pragma unroll
        for (int o = 16; o; o >>= 1) {
            su += __shfl_xor_sync(F, su, o);
            sq += __shfl_xor_sync(F, sq, o);
        }
        float dsum = sum2(acc);
        float dfull = dsum + __shfl_xor_sync(F, dsum, 16);
        float mu = su * (1.f/CZ);
        float rs = rsqrtf(sq * (1.f/CZ) - mu*mu + 1e-5f);
        if (l < 16)
            stage[w][pi][l] = rs * (dfull - mu * Svr) + Cvr;
    }
    __syncwarp();
    #pragma unroll
    for (int hh = 0; hh < NH; hh++) {
        if (l < PPW)
            out[(ll)hh * NN + pbase + l] = stage[w][l][hh];
    }
}

// ---------------- softmax ----------------
__global__ __launch_bounds__(256) void softmax_k(float* __restrict__ p) {
    float* x = p + (ll)blockIdx.x * NT;
    int t = threadIdx.x;
    float v0 = x[t], v1 = x[t+256], v2 = x[t+512];
    float mx = blkreduce(fmaxf(v0, fmaxf(v1, v2)), true);
    float e0 = __expf(v0 - mx), e1 = __expf(v1 - mx), e2 = __expf(v2 - mx);
    float s = blkreduce(e0 + e1 + e2, false);
    float inv = 1.f / s;
    x[t] = e0*inv; x[t+256] = e1*inv; x[t+512] = e2*inv;
}

// ---------------- tf32 tensor-core GEMM with fused epilogue ----------------
// FLG bits: 1=BVEC 2=MATB 4=MUL 8=ADD 16=ROWSCALE 32=STORE_TRANSPOSED
#define BM 128
#define BN 64
#define BKK 16

template<int ACT, int FLG>
__global__ __launch_bounds__(256) void tgemm_k(
    const float* __restrict__ A, int lda, ll sA,
    const float* __restrict__ W, int ldw, ll sW,
    float* __restrict__ C, int ldc, ll sC,
    const float* __restrict__ bvec,
    const float* __restrict__ matb, ll sMB, int ldmb,
    const float* __restrict__ mul, ll sMul, int ldmul,
    const float* __restrict__ addm, int ldadd,
    const float* __restrict__ rowsc,
    int N, int K, float scale)
{
    constexpr bool BVEC = FLG & 1, MATB = FLG & 2, MULF = FLG & 4,
                   ADDF = FLG & 8, ROWS = FLG & 16, STORET = FLG & 32;
    int zb = blockIdx.z;
    A += zb * sA; W += zb * sW; C += zb * sC;
    const float* mb = MATB ? matb + zb * sMB : nullptr;
    const float* ml = MULF ? mul + zb * sMul : nullptr;

    __shared__ float As[BM][20];
    __shared__ float Bs[BKK][72];
    int t = threadIdx.x;
    int m0 = blockIdx.y * BM, n0 = blockIdx.x * BN;
    int ar = t >> 2, ac = (t & 3) * 4;
    int br = t >> 4, bc = (t & 15) * 4;
    int nrem = N - n0;
    bool nfull = (nrem >= BN);

    int wid = t >> 5, lane = t & 31;
    int wm = (wid & 3) * 32, wn = (wid >> 2) * 32;
    int lr = lane >> 2, lc = lane & 3;

    float acc[2][4][4];
    #pragma unroll
    for (int i = 0; i < 2; i++)
        #pragma unroll
        for (int j = 0; j < 4; j++)
            #pragma unroll
            for (int q = 0; q < 4; q++) acc[i][j][q] = 0.f;

    float4 av0, av1, bv;
    // prologue load
    {
        av0 = *(const float4*)&A[(ll)(m0 + ar) * lda + ac];
        av1 = *(const float4*)&A[(ll)(m0 + ar + 64) * lda + ac];
        if (nfull) bv = *(const float4*)&W[(ll)br * ldw + n0 + bc];
        else {
            const float* wp = &W[(ll)br * ldw + n0];
            bv.x = (bc+0 < nrem) ? wp[bc+0] : 0.f;
            bv.y = (bc+1 < nrem) ? wp[bc+1] : 0.f;
            bv.z = (bc+2 < nrem) ? wp[bc+2] : 0.f;
            bv.w = (bc+3 < nrem) ? wp[bc+3] : 0.f;
        }
    }

    for (int k0 = 0; k0 < K; k0 += BKK) {
        *(float4*)&As[ar][ac]      = make_float4(t32(av0.x), t32(av0.y), t32(av0.z), t32(av0.w));
        *(float4*)&As[ar + 64][ac] = make_float4(t32(av1.x), t32(av1.y), t32(av1.z), t32(av1.w));
        *(float4*)&Bs[br][bc]      = make_float4(t32(bv.x),  t32(bv.y),  t32(bv.z),  t32(bv.w));
        __syncthreads();
        int kn = k0 + BKK;
        if (kn < K) {
            av0 = *(const float4*)&A[(ll)(m0 + ar) * lda + kn + ac];
            av1 = *(const float4*)&A[(ll)(m0 + ar + 64) * lda + kn + ac];
            if (nfull) bv = *(const float4*)&W[(ll)(kn + br) * ldw + n0 + bc];
            else {
                const float* wp = &W[(ll)(kn + br) * ldw + n0];
                bv.x = (bc+0 < nrem) ? wp[bc+0] : 0.f;
                bv.y = (bc+1 < nrem) ? wp[bc+1] : 0.f;
                bv.z = (bc+2 < nrem) ? wp[bc+2] : 0.f;
                bv.w = (bc+3 < nrem) ? wp[bc+3] : 0.f;
            }
        }
        #pragma unroll
        for (int ks = 0; ks < BKK; ks += 8) {
            unsigned a[2][4], b[4][2];
            #pragma unroll
            for (int mt = 0; mt < 2; mt++) {
                int r0 = wm + 16*mt + lr;
                a[mt][0] = __float_as_uint(As[r0    ][ks + lc]);
                a[mt][1] = __float_as_uint(As[r0 + 8][ks + lc]);
                a[mt][2] = __float_as_uint(As[r0    ][ks + lc + 4]);
                a[mt][3] = __float_as_uint(As[r0 + 8][ks + lc + 4]);
            }
            #pragma unroll
            for (int nt = 0; nt < 4; nt++) {
                int c0 = wn + 8*nt + lr;
                b[nt][0] = __float_as_uint(Bs[ks + lc    ][c0]);
                b[nt][1] = __float_as_uint(Bs[ks + lc + 4][c0]);
            }
            #pragma unroll
            for (int mt = 0; mt < 2; mt++)
                #pragma unroll
                for (int nt = 0; nt < 4; nt++) {
                    float* cc = acc[mt][nt];
                    asm volatile(
                        "mma.sync.aligned.m16n8k8.row.col.f32.tf32.tf32.f32 "
                        "{%0,%1,%2,%3}, {%4,%5,%6,%7}, {%8,%9}, {%0,%1,%2,%3};\n"
                        : "+f"(cc[0]), "+f"(cc[1]), "+f"(cc[2]), "+f"(cc[3])
                        : "r"(a[mt][0]), "r"(a[mt][1]), "r"(a[mt][2]), "r"(a[mt][3]),
                          "r"(b[nt][0]), "r"(b[nt][1]));
                }
        }
        __syncthreads();
    }

    auto ep = [&](int m, int n, float v) {
        if (n >= N) return;
        v *= scale;
        if (BVEC) v += bvec[n];
        if (MATB) v += mb[(ll)m * ldmb + n];
        if (ACT == 1) v = 1.f / (1.f + __expf(-v));
        else if (ACT == 2) v = v / (1.f + __expf(-v));
        if (MULF) v *= ml[(ll)m * ldmul + n];
        if (ROWS) v *= rowsc[m];
        if (ADDF) v += addm[(ll)m * ldadd + n];
        if (STORET) C[(ll)n * ldc + m] = v;
        else        C[(ll)m * ldc + n] = v;
    };
    #pragma unroll
    for (int mt = 0; mt < 2; mt++)
        #pragma unroll
        for (int nt = 0; nt < 4; nt++) {
            int mrow = m0 + wm + 16*mt + lr;
            int ncol = n0 + wn + 8*nt + 2*lc;
            float* cc = acc[mt][nt];
            ep(mrow,     ncol,     cc[0]);
            ep(mrow,     ncol + 1, cc[1]);
            ep(mrow + 8, ncol,     cc[2]);
            ep(mrow + 8, ncol + 1, cc[3]);
        }
}

// ---------------- host orchestration ----------------
#define SYM(p, name) do { void* _t; cudaGetSymbolAddress(&_t, name); p = (float*)_t; } while (0)
#define NUL ((const float*)nullptr)

extern "C" void kernel_launch(void* const* d_in, const int* in_sizes, int n_in,
                              void* d_out, int out_size) {
    const float* a    = (const float*)d_in[0];
    const float* s    = (const float*)d_in[1];
    const float* z    = (const float*)d_in[2];
    const int*   mask = (const int*)  d_in[3];
    const float* a_slng  = (const float*)d_in[4];
    const float* a_gw    = (const float*)d_in[5];
    const float* a_gb    = (const float*)d_in[6];
    const float* a_sw    = (const float*)d_in[7];
    const float* wq   = (const float*)d_in[8];
    const float* bq   = (const float*)d_in[9];
    const float* wk   = (const float*)d_in[10];
    const float* wv   = (const float*)d_in[11];
    const float* zlng = (const float*)d_in[12];
    const float* zlnb = (const float*)d_in[13];
    const float* wb   = (const float*)d_in[14];
    const float* wg   = (const float*)d_in[15];
    const float* wo   = (const float*)d_in[16];
    const float* aogw = (const float*)d_in[17];
    const float* aogb = (const float*)d_in[18];
    const float* t_slng = (const float*)d_in[19];
    const float* t_gw   = (const float*)d_in[20];
    const float* t_gb   = (const float*)d_in[21];
    const float* t_sw   = (const float*)d_in[22];
    const float* w1   = (const float*)d_in[23];
    const float* w2   = (const float*)d_in[24];
    const float* two  = (const float*)d_in[25];
    const float* togw = (const float*)d_in[26];
    const float* togb = (const float*)d_in[27];
    float* out = (float*)d_out;

    float *slnA,*slnT,*gateA,*skipA,*outGA,*gateT,*skipT,*outGT,*aln;
    float *qb,*kT,*vb,*gb,*logits,*og,*anew,*h1,*hid,*maskb,*maskf;
    SYM(slnA, g_slnA); SYM(slnT, g_slnT);
    SYM(gateA, g_gateA); SYM(skipA, g_skipA); SYM(outGA, g_outGA);
    SYM(gateT, g_gateT); SYM(skipT, g_skipT); SYM(outGT, g_outGT);
    SYM(aln, g_aln);
    SYM(qb, g_q); SYM(kT, g_kT); SYM(vb, g_v); SYM(gb, g_g);
    SYM(logits, g_logits); SYM(og, g_og); SYM(anew, g_anew);
    SYM(h1, g_h1); SYM(hid, g_hid);
    SYM(maskb, g_maskb); SYM(maskf, g_maskf);

    dim3 blk(256);
    dim3 g12(12, 6, 1), g24(24, 6, 1), gH(12, 6, 16), gO(1, 6, 16);

    prep_k<<<1, 256>>>(mask, zlng, zlnb, wb);
    lns_k<<<NT, 128>>>(s, a_slng, t_slng, slnA, slnT);

    // s-conditioned gates / skips (K=384)
    tgemm_k<1,1><<<g12,blk>>>(slnA,CS,0, a_gw,CA,0, gateA,CA,0, a_gb, NUL,0,0, NUL,0,0, NUL,0, NUL, CA,CS,1.f);
    tgemm_k<0,0><<<g12,blk>>>(slnA,CS,0, a_sw,CA,0, skipA,CA,0, NUL, NUL,0,0, NUL,0,0, NUL,0, NUL, CA,CS,1.f);
    tgemm_k<1,1><<<g12,blk>>>(s,   CS,0, aogw,CA,0, outGA,CA,0, aogb, NUL,0,0, NUL,0,0, NUL,0, NUL, CA,CS,1.f);
    tgemm_k<1,1><<<g12,blk>>>(slnT,CS,0, t_gw,CA,0, gateT,CA,0, t_gb, NUL,0,0, NUL,0,0, NUL,0, NUL, CA,CS,1.f);
    tgemm_k<0,0><<<g12,blk>>>(slnT,CS,0, t_sw,CA,0, skipT,CA,0, NUL, NUL,0,0, NUL,0,0, NUL,0, NUL, CA,CS,1.f);
    tgemm_k<1,1><<<g12,blk>>>(s,   CS,0, togw,CA,0, outGT,CA,0, togb, NUL,0,0, NUL,0,0, NUL,0, NUL, CA,CS,1.f);

    // a_ln = gateA * LN(a) + skipA
    adaln_k<<<NT, 256>>>(a, gateA, skipA, aln);

    // projections (K=768)
    tgemm_k<0,1 ><<<g12,blk>>>(aln,CA,0, wq,CA,0, qb,CA,0, bq,  NUL,0,0, NUL,0,0, NUL,0, NUL, CA,CA,1.f);
    tgemm_k<0,32><<<g12,blk>>>(aln,CA,0, wk,CA,0, kT,NT,0, NUL, NUL,0,0, NUL,0,0, NUL,0, NUL, CA,CA,1.f);
    tgemm_k<0,0 ><<<g12,blk>>>(aln,CA,0, wv,CA,0, vb,CA,0, NUL, NUL,0,0, NUL,0,0, NUL,0, NUL, CA,CA,1.f);
    tgemm_k<1,0 ><<<g12,blk>>>(aln,CA,0, wg,CA,0, gb,CA,0, NUL, NUL,0,0, NUL,0,0, NUL,0, NUL, CA,CA,1.f);

    // pair bias -> logits buffer [h][q][k]
    pairbias_k<<<NN/(8*PPW), 256>>>(z, logits);

    // logits[h] = q_h @ kT_h / sqrt(48) + maskb + bias (in place)
    tgemm_k<0,3><<<gH,blk>>>(qb,CA,48, kT,NT,(ll)48*NT, logits,NT,(ll)NN,
                             maskb, logits,(ll)NN,NT, NUL,0,0, NUL,0, NUL,
                             NT, CH, 0.14433756729740643f);

    softmax_k<<<NH*NT, 256>>>(logits);

    // o_h = attn_h @ v_h, gated by g
    tgemm_k<0,4><<<gO,blk>>>(logits,NT,(ll)NN, vb,CA,48, og,CA,48,
                             NUL, NUL,0,0, gb,48,CA, NUL,0, NUL,
                             CH, NT, 1.f);

    // a_new = a + outGA * (og @ wo)
    tgemm_k<0,12><<<g12,blk>>>(og,CA,0, wo,CA,0, anew,CA,0,
                               NUL, NUL,0,0, outGA,0,CA, a,CA, NUL,
                               CA, CA, 1.f);

    // t_ln = gateT * LN(a_new) + skipT
    adaln_k<<<NT, 256>>>(anew, gateT, skipT, aln);

    // SwiGLU
    tgemm_k<2,0><<<g24,blk>>>(aln,CA,0, w1,1536,0, h1,1536,0,
                              NUL, NUL,0,0, NUL,0,0, NUL,0, NUL, 1536,CA,1.f);
    tgemm_k<0,4><<<g24,blk>>>(aln,CA,0, w2,1536,0, hid,1536,0,
                              NUL, NUL,0,0, h1,0,1536, NUL,0, NUL, 1536,CA,1.f);

    // out = a_new + maskf * outGT * (hid @ tr_wo)
    tgemm_k<0,28><<<g12,blk>>>(hid,1536,0, two,CA,0, out,CA,0,
                               NUL, NUL,0,0, outGT,0,CA, anew,CA, maskf,
                               CA, 1536, 1.f);
}

// round 3
// speedup vs baseline: 2.0305x; 1.3940x over previous
#include <cuda_runtime.h>
#include <math.h>

typedef long long ll;
typedef unsigned long long ull;

#define NT 768
#define CA 768
#define CS 384
#define CZ 128
#define NH 16
#define CH 48
#define NN (768*768)

// ---------------- scratch ----------------
__device__ float g_slnA[NT*CS], g_slnT[NT*CS];
__device__ float g_gateA[NT*CA], g_skipA[NT*CA], g_outGA[NT*CA];
__device__ float g_gateT[NT*CA], g_skipT[NT*CA], g_outGT[NT*CA];
__device__ float g_aln[NT*CA];
__device__ float g_q[NT*CA], g_kT[NT*CA], g_v[NT*CA], g_g[NT*CA];
__device__ float g_logits[NH*NN];
__device__ float g_og[NT*CA];
__device__ float g_anew[NT*CA];
__device__ float g_h1[NT*1536], g_hid[NT*1536];
__device__ float g_Wp[NH*CZ], g_Sv[NH], g_Cv[NH], g_maskb[NT], g_maskf[NT];

// ---------------- helpers ----------------
__device__ __forceinline__ unsigned cvt32(float x) {
    unsigned u; asm("cvt.rna.tf32.f32 %0, %1;" : "=r"(u) : "f"(x));
    return u;
}
__device__ __forceinline__ ull pk2(float x, float y) {
    ull r; asm("mov.b64 %0, {%1, %2};" : "=l"(r) : "f"(x), "f"(y)); return r;
}
__device__ __forceinline__ void fma2(ull &d, ull a, ull b) {
    asm("fma.rn.f32x2 %0, %1, %2, %0;" : "+l"(d) : "l"(a), "l"(b));
}
__device__ __forceinline__ float sum2(ull v) {
    float x, y; asm("mov.b64 {%0, %1}, %2;" : "=f"(x), "=f"(y) : "l"(v));
    return x + y;
}
__device__ __forceinline__ unsigned su32(const void* p) {
    return (unsigned)__cvta_generic_to_shared(p);
}
__device__ __forceinline__ void cpa16(unsigned dst, const float* src, int bytes) {
    asm volatile("cp.async.ca.shared.global [%0], [%1], 16, %2;\n"
                 :: "r"(dst), "l"(src), "r"(bytes));
}
__device__ __forceinline__ void cpcommit() { asm volatile("cp.async.commit_group;\n"); }
template<int Ng> __device__ __forceinline__ void cpwait() {
    asm volatile("cp.async.wait_group %0;\n" :: "n"(Ng));
}

__device__ __forceinline__ float blkreduce(float v, bool domax) {
    __shared__ float sm[32];
    const unsigned F = 0xffffffffu;
    #pragma unroll
    for (int o = 16; o; o >>= 1) {
        float u = __shfl_xor_sync(F, v, o);
        v = domax ? fmaxf(v, u) : v + u;
    }
    __syncthreads();
    if ((threadIdx.x & 31) == 0) sm[threadIdx.x >> 5] = v;
    __syncthreads();
    int nw = blockDim.x >> 5;
    if (threadIdx.x < 32) {
        float u = (threadIdx.x < nw) ? sm[threadIdx.x] : (domax ? -3.4e38f : 0.f);
        #pragma unroll
        for (int o = 16; o; o >>= 1) {
            float w = __shfl_xor_sync(F, u, o);
            u = domax ? fmaxf(u, w) : u + w;
        }
        if (threadIdx.x == 0) sm[0] = u;
    }
    __syncthreads();
    return sm[0];
}

// ---------------- prep ----------------
__global__ void prep_k(const int* __restrict__ mask, const float* __restrict__ zg,
                       const float* __restrict__ zb, const float* __restrict__ wb) {
    int t = threadIdx.x;
    for (int i = t; i < NT; i += 256) {
        float m = (float)mask[i];
        g_maskf[i] = m;
        g_maskb[i] = (m - 1.f) * 1e9f;
    }
    for (int i = t; i < NH*CZ; i += 256) {
        int h = i >> 7, c = i & 127;
        g_Wp[i] = zg[c] * wb[c*NH + h];
    }
    if (t < NH) {
        float s = 0.f, cs = 0.f;
        for (int c = 0; c < CZ; c++) {
            s  += zg[c] * wb[c*NH + t];
            cs += zb[c] * wb[c*NH + t];
        }
        g_Sv[t] = s; g_Cv[t] = cs;
    }
}

// ---------------- LN(s) dual scale ----------------
__global__ __launch_bounds__(128) void lns_k(const float* __restrict__ s,
                                             const float* __restrict__ gA,
                                             const float* __restrict__ gT,
                                             float* __restrict__ oA, float* __restrict__ oT) {
    int r = blockIdx.x, t = threadIdx.x;
    const float* x = s + (ll)r * CS;
    float v[3]; float su = 0.f, q = 0.f;
    #pragma unroll
    for (int i = 0; i < 3; i++) { v[i] = x[t + 128*i]; su += v[i]; q += v[i]*v[i]; }
    su = blkreduce(su, false);
    q  = blkreduce(q, false);
    float mu = su * (1.f/CS);
    float rs = rsqrtf(q * (1.f/CS) - mu*mu + 1e-5f);
    ll base = (ll)r * CS;
    #pragma unroll
    for (int i = 0; i < 3; i++) {
        int c = t + 128*i;
        float xh = (v[i] - mu) * rs;
        oA[base + c] = xh * gA[c];
        oT[base + c] = xh * gT[c];
    }
}

// ---------------- AdaLN combine ----------------
__global__ __launch_bounds__(256) void adaln_k(const float* __restrict__ a,
                                               const float* __restrict__ gate,
                                               const float* __restrict__ skip,
                                               float* __restrict__ out) {
    int r = blockIdx.x, t = threadIdx.x;
    const float* x = a + (ll)r * CA;
    float v[3]; float su = 0.f, q = 0.f;
    #pragma unroll
    for (int i = 0; i < 3; i++) { v[i] = x[t + 256*i]; su += v[i]; q += v[i]*v[i]; }
    su = blkreduce(su, false);
    q  = blkreduce(q, false);
    float mu = su * (1.f/CA);
    float rs = rsqrtf(q * (1.f/CA) - mu*mu + 1e-5f);
    ll base = (ll)r * CA;
    #pragma unroll
    for (int i = 0; i < 3; i++) {
        int c = t + 256*i;
        out[base + c] = gate[base + c] * ((v[i] - mu) * rs) + skip[base + c];
    }
}

// ---------------- pair bias (register-W, warp-per-pair, f32x2) ----------------
#define PPW 16
__global__ __launch_bounds__(256) void pairbias_k(const float* __restrict__ z,
                                                  float* __restrict__ out) {
    __shared__ float stage[8][PPW][17];
    int t = threadIdx.x, w = t >> 5, l = t & 31;
    int h = l & 15, half = l >> 4;
    const unsigned F = 0xffffffffu;

    ull wreg[32];
    {
        const float4* wrow = (const float4*)(&g_Wp[h*CZ + half*64]);
        #pragma unroll
        for (int j = 0; j < 16; j++) {
            float4 wv = wrow[j];
            wreg[2*j]   = pk2(wv.x, wv.y);
            wreg[2*j+1] = pk2(wv.z, wv.w);
        }
    }
    float Svr = g_Sv[h], Cvr = g_Cv[h];
    ll pbase = ((ll)blockIdx.x * 8 + w) * PPW;

    for (int pi = 0; pi < PPW; pi++) {
        ll p = pbase + pi;
        const float4* zr = (const float4*)(z + p * CZ);
        float4 zc = zr[l];
        float su = zc.x + zc.y + zc.z + zc.w;
        float sq = zc.x*zc.x + zc.y*zc.y + zc.z*zc.z + zc.w*zc.w;
        ull acc = 0;
        const float4* zh = zr + half * 16;
        #pragma unroll
        for (int j = 0; j < 16; j++) {
            float4 zv = zh[j];
            fma2(acc, pk2(zv.x, zv.y), wreg[2*j]);
            fma2(acc, pk2(zv.z, zv.w), wreg[2*j+1]);
        }
        #pragma unroll
        for (int o = 16; o; o >>= 1) {
            su += __shfl_xor_sync(F, su, o);
            sq += __shfl_xor_sync(F, sq, o);
        }
        float dsum = sum2(acc);
        float dfull = dsum + __shfl_xor_sync(F, dsum, 16);
        float mu = su * (1.f/CZ);
        float rs = rsqrtf(sq * (1.f/CZ) - mu*mu + 1e-5f);
        if (l < 16)
            stage[w][pi][l] = rs * (dfull - mu * Svr) + Cvr;
    }
    __syncwarp();
    #pragma unroll
    for (int hh = 0; hh < NH; hh++) {
        if (l < PPW)
            out[(ll)hh * NN + pbase + l] = stage[w][l][hh];
    }
}

// ---------------- softmax ----------------
__global__ __launch_bounds__(256) void softmax_k(float* __restrict__ p) {
    float* x = p + (ll)blockIdx.x * NT;
    int t = threadIdx.x;
    float v0 = x[t], v1 = x[t+256], v2 = x[t+512];
    float mx = blkreduce(fmaxf(v0, fmaxf(v1, v2)), true);
    float e0 = __expf(v0 - mx), e1 = __expf(v1 - mx), e2 = __expf(v2 - mx);
    float s = blkreduce(e0 + e1 + e2, false);
    float inv = 1.f / s;
    x[t] = e0*inv; x[t+256] = e1*inv; x[t+512] = e2*inv;
}

// ---------------- batched tf32 MMA GEMM, cp.async 3-stage ----------------
// flags: 1=BVEC 2=MATB 4=MUL 8=ADD 16=ROWSCALE 32=STORE_TRANSPOSED
struct ZArg {
    const float *A, *W, *bvec, *matb, *mul, *addm, *rowsc;
    float *C;
    int lda, ldw, ldc, ldmb, ldmul, ldadd;
    int actf;   // act | (flags<<4)
    float scale;
    int N, K;
};
struct ZPack { ZArg z[16]; };

template<int BMv>
__global__ __launch_bounds__(256) void bgemm_k(ZPack P) {
    const ZArg za = P.z[blockIdx.z];
    constexpr int S = 3;
    __shared__ __align__(16) float As[S][BMv][20];
    __shared__ __align__(16) float Bs[S][16][68];
    int t = threadIdx.x;
    int m0 = blockIdx.y * BMv, n0 = blockIdx.x * 64;
    const int K = za.K, N = za.N;
    int niter = K >> 4;

    auto load_stage = [&](int st, int k0) {
        #pragma unroll
        for (int i = 0; i < BMv/64; i++) {
            int c = t + 256*i;
            int row = c >> 2, kc = (c & 3) * 4;
            cpa16(su32(&As[st][row][kc]),
                  za.A + (ll)(m0 + row) * za.lda + k0 + kc, 16);
        }
        {
            int row = t >> 4, nc = (t & 15) * 4;
            int rem = N - (n0 + nc);
            int bytes = (rem >= 4) ? 16 : (rem > 0 ? rem * 4 : 0);
            const float* src = za.W + (ll)(k0 + row) * za.ldw + n0 + nc;
            if (bytes == 0) src = za.W;
            cpa16(su32(&Bs[st][row][nc]), src, bytes);
        }
    };

    #pragma unroll
    for (int i = 0; i < S-1; i++) {
        if (i < niter) load_stage(i, i * 16);
        cpcommit();
    }

    int wid = t >> 5, lane = t & 31;
    int lr = lane >> 2, lc = lane & 3;
    constexpr int NTW = (BMv == 128) ? 4 : 2;
    int wm = (BMv == 128) ? (wid & 3) * 32 : (wid & 1) * 32;
    int wn = (BMv == 128) ? (wid >> 2) * 32 : (wid >> 1) * 16;

    float acc[2][NTW][4] = {};

    for (int it = 0; it < niter; it++) {
        cpwait<S-2>();
        __syncthreads();
        int pf = it + S - 1;
        if (pf < niter) load_stage(pf % S, pf * 16);
        cpcommit();
        int st = it % S;
        #pragma unroll
        for (int ks = 0; ks < 16; ks += 8) {
            unsigned afr[2][4], bfr[NTW][2];
            #pragma unroll
            for (int mt = 0; mt < 2; mt++) {
                int r0 = wm + 16*mt + lr;
                afr[mt][0] = cvt32(As[st][r0    ][ks + lc]);
                afr[mt][1] = cvt32(As[st][r0 + 8][ks + lc]);
                afr[mt][2] = cvt32(As[st][r0    ][ks + lc + 4]);
                afr[mt][3] = cvt32(As[st][r0 + 8][ks + lc + 4]);
            }
            #pragma unroll
            for (int nt = 0; nt < NTW; nt++) {
                int c0 = wn + 8*nt + lr;
                bfr[nt][0] = cvt32(Bs[st][ks + lc    ][c0]);
                bfr[nt][1] = cvt32(Bs[st][ks + lc + 4][c0]);
            }
            #pragma unroll
            for (int mt = 0; mt < 2; mt++)
                #pragma unroll
                for (int nt = 0; nt < NTW; nt++) {
                    float* cc = acc[mt][nt];
                    asm volatile(
                        "mma.sync.aligned.m16n8k8.row.col.f32.tf32.tf32.f32 "
                        "{%0,%1,%2,%3}, {%4,%5,%6,%7}, {%8,%9}, {%0,%1,%2,%3};\n"
                        : "+f"(cc[0]), "+f"(cc[1]), "+f"(cc[2]), "+f"(cc[3])
                        : "r"(afr[mt][0]), "r"(afr[mt][1]), "r"(afr[mt][2]), "r"(afr[mt][3]),
                          "r"(bfr[nt][0]), "r"(bfr[nt][1]));
                }
        }
        __syncthreads();
    }

    int act = za.actf & 15, flg = za.actf >> 4;
    auto ep = [&](int m, int n, float v) {
        if (n >= N) return;
        v *= za.scale;
        if (flg & 1)  v += za.bvec[n];
        if (flg & 2)  v += za.matb[(ll)m * za.ldmb + n];
        if (act == 1) v = 1.f / (1.f + __expf(-v));
        else if (act == 2) v = v / (1.f + __expf(-v));
        if (flg & 4)  v *= za.mul[(ll)m * za.ldmul + n];
        if (flg & 16) v *= za.rowsc[m];
        if (flg & 8)  v += za.addm[(ll)m * za.ldadd + n];
        if (flg & 32) za.C[(ll)n * za.ldc + m] = v;
        else          za.C[(ll)m * za.ldc + n] = v;
    };
    #pragma unroll
    for (int mt = 0; mt < 2; mt++)
        #pragma unroll
        for (int nt = 0; nt < NTW; nt++) {
            int mrow = m0 + wm + 16*mt + lr;
            int ncol = n0 + wn + 8*nt + 2*lc;
            float* cc = acc[mt][nt];
            ep(mrow,     ncol,     cc[0]);
            ep(mrow,     ncol + 1, cc[1]);
            ep(mrow + 8, ncol,     cc[2]);
            ep(mrow + 8, ncol + 1, cc[3]);
        }
}

// ---------------- host orchestration ----------------
#define SYM(p, name) do { void* _t; cudaGetSymbolAddress(&_t, name); p = (float*)_t; } while (0)

static ZArg mk(const float* A, int lda, const float* W, int ldw, float* C, int ldc,
               int N, int K, float scale, int act, int flg,
               const float* bvec = nullptr,
               const float* matb = nullptr, int ldmb = 0,
               const float* mul = nullptr, int ldmul = 0,
               const float* addm = nullptr, int ldadd = 0,
               const float* rowsc = nullptr) {
    ZArg z;
    z.A = A; z.W = W; z.C = C; z.bvec = bvec; z.matb = matb; z.mul = mul;
    z.addm = addm; z.rowsc = rowsc;
    z.lda = lda; z.ldw = ldw; z.ldc = ldc; z.ldmb = ldmb; z.ldmul = ldmul; z.ldadd = ldadd;
    z.actf = act | (flg << 4); z.scale = scale; z.N = N; z.K = K;
    return z;
}

extern "C" void kernel_launch(void* const* d_in, const int* in_sizes, int n_in,
                              void* d_out, int out_size) {
    const float* a    = (const float*)d_in[0];
    const float* s    = (const float*)d_in[1];
    const float* z    = (const float*)d_in[2];
    const int*   mask = (const int*)  d_in[3];
    const float* a_slng  = (const float*)d_in[4];
    const float* a_gw    = (const float*)d_in[5];
    const float* a_gb    = (const float*)d_in[6];
    const float* a_sw    = (const float*)d_in[7];
    const float* wq   = (const float*)d_in[8];
    const float* bq   = (const float*)d_in[9];
    const float* wk   = (const float*)d_in[10];
    const float* wv   = (const float*)d_in[11];
    const float* zlng = (const float*)d_in[12];
    const float* zlnb = (const float*)d_in[13];
    const float* wb   = (const float*)d_in[14];
    const float* wg   = (const float*)d_in[15];
    const float* wo   = (const float*)d_in[16];
    const float* aogw = (const float*)d_in[17];
    const float* aogb = (const float*)d_in[18];
    const float* t_slng = (const float*)d_in[19];
    const float* t_gw   = (const float*)d_in[20];
    const float* t_gb   = (const float*)d_in[21];
    const float* t_sw   = (const float*)d_in[22];
    const float* w1   = (const float*)d_in[23];
    const float* w2   = (const float*)d_in[24];
    const float* two  = (const float*)d_in[25];
    const float* togw = (const float*)d_in[26];
    const float* togb = (const float*)d_in[27];
    float* out = (float*)d_out;

    float *slnA,*slnT,*gateA,*skipA,*outGA,*gateT,*skipT,*outGT,*aln;
    float *qb,*kT,*vb,*gb,*logits,*og,*anew,*h1,*hid,*maskb,*maskf;
    SYM(slnA, g_slnA); SYM(slnT, g_slnT);
    SYM(gateA, g_gateA); SYM(skipA, g_skipA); SYM(outGA, g_outGA);
    SYM(gateT, g_gateT); SYM(skipT, g_skipT); SYM(outGT, g_outGT);
    SYM(aln, g_aln);
    SYM(qb, g_q); SYM(kT, g_kT); SYM(vb, g_v); SYM(gb, g_g);
    SYM(logits, g_logits); SYM(og, g_og); SYM(anew, g_anew);
    SYM(h1, g_h1); SYM(hid, g_hid);
    SYM(maskb, g_maskb); SYM(maskf, g_maskf);

    prep_k<<<1, 256>>>(mask, zlng, zlnb, wb);
    lns_k<<<NT, 128>>>(s, a_slng, t_slng, slnA, slnT);

    // ---- batch 1: six s-conditioned gate/skip GEMMs (M=768,N=768,K=384) ----
    {
        ZPack P;
        P.z[0] = mk(slnA, CS, a_gw, CA, gateA, CA, CA, CS, 1.f, 1, 1, a_gb);
        P.z[1] = mk(slnA, CS, a_sw, CA, skipA, CA, CA, CS, 1.f, 0, 0);
        P.z[2] = mk(s,    CS, aogw, CA, outGA, CA, CA, CS, 1.f, 1, 1, aogb);
        P.z[3] = mk(slnT, CS, t_gw, CA, gateT, CA, CA, CS, 1.f, 1, 1, t_gb);
        P.z[4] = mk(slnT, CS, t_sw, CA, skipT, CA, CA, CS, 1.f, 0, 0);
        P.z[5] = mk(s,    CS, togw, CA, outGT, CA, CA, CS, 1.f, 1, 1, togb);
        bgemm_k<128><<<dim3(12,6,6), 256>>>(P);
    }

    adaln_k<<<NT, 256>>>(a, gateA, skipA, aln);

    // ---- batch 2: QKVG projections (M=768,N=768,K=768) ----
    {
        ZPack P;
        P.z[0] = mk(aln, CA, wq, CA, qb, CA, CA, CA, 1.f, 0, 1, bq);
        P.z[1] = mk(aln, CA, wk, CA, kT, NT, CA, CA, 1.f, 0, 32);
        P.z[2] = mk(aln, CA, wv, CA, vb, CA, CA, CA, 1.f, 0, 0);
        P.z[3] = mk(aln, CA, wg, CA, gb, CA, CA, CA, 1.f, 1, 0);
        bgemm_k<128><<<dim3(12,6,4), 256>>>(P);
    }

    pairbias_k<<<NN/(8*PPW), 256>>>(z, logits);

    // ---- batch 3: logits per head (in-place add of pair bias + mask bias) ----
    {
        ZPack P;
        for (int h = 0; h < NH; h++)
            P.z[h] = mk(qb + 48*h, CA, kT + (ll)48*NT*h, NT,
                        logits + (ll)NN*h, NT, NT, CH, 0.14433756729740643f,
                        0, 1 | 2, maskb, logits + (ll)NN*h, NT);
        bgemm_k<128><<<dim3(12,6,16), 256>>>(P);
    }

    softmax_k<<<NH*NT, 256>>>(logits);

    // ---- batch 4: AV per head, gated by g ----
    {
        ZPack P;
        for (int h = 0; h < NH; h++)
            P.z[h] = mk(logits + (ll)NN*h, NT, vb + 48*h, CA,
                        og + 48*h, CA, CH, NT, 1.f,
                        0, 4, nullptr, nullptr, 0, gb + 48*h, CA);
        bgemm_k<64><<<dim3(1,12,16), 256>>>(P);
    }

    // ---- a_new = a + outGA * (og @ wo) ----
    {
        ZPack P;
        P.z[0] = mk(og, CA, wo, CA, anew, CA, CA, CA, 1.f,
                    0, 4 | 8, nullptr, nullptr, 0, outGA, CA, a, CA);
        bgemm_k<64><<<dim3(12,12,1), 256>>>(P);
    }

    adaln_k<<<NT, 256>>>(anew, gateT, skipT, aln);

    // ---- SwiGLU ----
    {
        ZPack P;
        P.z[0] = mk(aln, CA, w1, 1536, h1, 1536, 1536, CA, 1.f, 2, 0);
        bgemm_k<128><<<dim3(24,6,1), 256>>>(P);
    }
    {
        ZPack P;
        P.z[0] = mk(aln, CA, w2, 1536, hid, 1536, 1536, CA, 1.f,
                    0, 4, nullptr, nullptr, 0, h1, 1536);
        bgemm_k<128><<<dim3(24,6,1), 256>>>(P);
    }

    // ---- out = a_new + maskf * outGT * (hid @ tr_wo) ----
    {
        ZPack P;
        P.z[0] = mk(hid, 1536, two, CA, out, CA, CA, 1536, 1.f,
                    0, 4 | 8 | 16, nullptr, nullptr, 0, outGT, CA, anew, CA, maskf);
        bgemm_k<64><<<dim3(12,12,1), 256>>>(P);
    }
}

// round 6
// speedup vs baseline: 2.2271x; 1.0968x over previous
#include <cuda_runtime.h>
#include <cuda_bf16.h>
#include <math.h>

typedef long long ll;
typedef unsigned long long ull;

#define NT 768
#define CA 768
#define CS 384
#define CZ 128
#define NH 16
#define CH 48
#define NN (768*768)

// ---------------- fp32 scratch ----------------
__device__ float g_gateA[NT*CA], g_skipA[NT*CA], g_outGA[NT*CA];
__device__ float g_gateT[NT*CA], g_skipT[NT*CA], g_outGT[NT*CA];
__device__ float g_logits[NH*NN];
__device__ float g_anew[NT*CA];
__device__ float g_Wp[NH*CZ], g_Sv[NH], g_Cv[NH], g_maskb[NT], g_maskf[NT];

// ---------------- bf16 scratch ----------------
__device__ __nv_bfloat16 b_slnA[NT*CS], b_slnT[NT*CS], b_s[NT*CS];
__device__ __nv_bfloat16 b_aln[NT*CA], b_q[NT*CA], b_k[NT*CA];
__device__ __nv_bfloat16 b_vT[CA*NT], b_g[NT*CA];
__device__ __nv_bfloat16 b_probs[NH*NN];
__device__ __nv_bfloat16 b_og[NT*CA], b_h1[NT*1536], b_hid[NT*1536];
__device__ __nv_bfloat16 b_wpool[8257536];

// ---------------- helpers ----------------
__device__ __forceinline__ ull pk2(float x, float y) {
    ull r; asm("mov.b64 %0, {%1, %2};" : "=l"(r) : "f"(x), "f"(y)); return r;
}
__device__ __forceinline__ void fma2(ull &d, ull a, ull b) {
    asm("fma.rn.f32x2 %0, %1, %2, %0;" : "+l"(d) : "l"(a), "l"(b));
}
__device__ __forceinline__ float sum2(ull v) {
    float x, y; asm("mov.b64 {%0, %1}, %2;" : "=f"(x), "=f"(y) : "l"(v));
    return x + y;
}
__device__ __forceinline__ unsigned su32(const void* p) {
    return (unsigned)__cvta_generic_to_shared(p);
}
__device__ __forceinline__ void cpa16(unsigned dst, const void* src, int bytes) {
    asm volatile("cp.async.ca.shared.global [%0], [%1], 16, %2;\n"
                 :: "r"(dst), "l"(src), "r"(bytes));
}
__device__ __forceinline__ void cpcommit() { asm volatile("cp.async.commit_group;\n"); }
template<int Ng> __device__ __forceinline__ void cpwait() {
    asm volatile("cp.async.wait_group %0;\n" :: "n"(Ng));
}

__device__ __forceinline__ float blkreduce(float v, bool domax) {
    __shared__ float sm[32];
    const unsigned F = 0xffffffffu;
    #pragma unroll
    for (int o = 16; o; o >>= 1) {
        float u = __shfl_xor_sync(F, v, o);
        v = domax ? fmaxf(v, u) : v + u;
    }
    __syncthreads();
    if ((threadIdx.x & 31) == 0) sm[threadIdx.x >> 5] = v;
    __syncthreads();
    int nw = blockDim.x >> 5;
    if (threadIdx.x < 32) {
        float u = (threadIdx.x < nw) ? sm[threadIdx.x] : (domax ? -3.4e38f : 0.f);
        #pragma unroll
        for (int o = 16; o; o >>= 1) {
            float w = __shfl_xor_sync(F, u, o);
            u = domax ? fmaxf(u, w) : u + w;
        }
        if (threadIdx.x == 0) sm[0] = u;
    }
    __syncthreads();
    return sm[0];
}

// ---------------- prep: mask, folded pair-bias weights ----------------
__global__ void prep_k(const int* __restrict__ mask, const float* __restrict__ zg,
                       const float* __restrict__ zb, const float* __restrict__ wb) {
    int t = threadIdx.x;
    for (int i = t; i < NT; i += 256) {
        float m = (float)mask[i];
        g_maskf[i] = m;
        g_maskb[i] = (m - 1.f) * 1e9f;
    }
    for (int i = t; i < NH*CZ; i += 256) {
        int h = i >> 7, c = i & 127;
        g_Wp[i] = zg[c] * wb[c*NH + h];
    }
    if (t < NH) {
        float s = 0.f, cs = 0.f;
        for (int c = 0; c < CZ; c++) {
            s  += zg[c] * wb[c*NH + t];
            cs += zb[c] * wb[c*NH + t];
        }
        g_Sv[t] = s; g_Cv[t] = cs;
    }
}

// ---------------- weight transpose + bf16 convert ----------------
struct TArg { const float* src; __nv_bfloat16* dst; int K; int N; };
struct TPack { TArg t[14]; };

__global__ __launch_bounds__(256) void trans_k(TPack P) {
    TArg ta = P.t[blockIdx.z];
    int x0 = blockIdx.x * 32, y0 = blockIdx.y * 32;
    if (x0 >= ta.N || y0 >= ta.K) return;
    __shared__ float tile[32][33];
    int tx = threadIdx.x & 31, ty = threadIdx.x >> 5;  // 32x8
    #pragma unroll
    for (int i = 0; i < 32; i += 8) {
        int k = y0 + ty + i, n = x0 + tx;
        if (k < ta.K && n < ta.N) tile[ty + i][tx] = ta.src[(ll)k * ta.N + n];
    }
    __syncthreads();
    #pragma unroll
    for (int i = 0; i < 32; i += 8) {
        int n = x0 + ty + i, k = y0 + tx;
        if (n < ta.N && k < ta.K)
            ta.dst[(ll)n * ta.K + k] = __float2bfloat16_rn(tile[tx][ty + i]);
    }
}

// ---------------- LN(s) dual scale + bf16 s copy ----------------
__global__ __launch_bounds__(128) void lns_k(const float* __restrict__ s,
                                             const float* __restrict__ gA,
                                             const float* __restrict__ gT) {
    int r = blockIdx.x, t = threadIdx.x;
    const float* x = s + (ll)r * CS;
    float v[3]; float su = 0.f, q = 0.f;
    #pragma unroll
    for (int i = 0; i < 3; i++) { v[i] = x[t + 128*i]; su += v[i]; q += v[i]*v[i]; }
    su = blkreduce(su, false);
    q  = blkreduce(q, false);
    float mu = su * (1.f/CS);
    float rs = rsqrtf(q * (1.f/CS) - mu*mu + 1e-5f);
    ll base = (ll)r * CS;
    #pragma unroll
    for (int i = 0; i < 3; i++) {
        int c = t + 128*i;
        float xh = (v[i] - mu) * rs;
        b_slnA[base + c] = __float2bfloat16_rn(xh * gA[c]);
        b_slnT[base + c] = __float2bfloat16_rn(xh * gT[c]);
        b_s[base + c]    = __float2bfloat16_rn(v[i]);
    }
}

// ---------------- AdaLN combine -> bf16 ----------------
__global__ __launch_bounds__(256) void adaln_k(const float* __restrict__ a,
                                               const float* __restrict__ gate,
                                               const float* __restrict__ skip,
                                               __nv_bfloat16* __restrict__ out) {
    int r = blockIdx.x, t = threadIdx.x;
    const float* x = a + (ll)r * CA;
    float v[3]; float su = 0.f, q = 0.f;
    #pragma unroll
    for (int i = 0; i < 3; i++) { v[i] = x[t + 256*i]; su += v[i]; q += v[i]*v[i]; }
    su = blkreduce(su, false);
    q  = blkreduce(q, false);
    float mu = su * (1.f/CA);
    float rs = rsqrtf(q * (1.f/CA) - mu*mu + 1e-5f);
    ll base = (ll)r * CA;
    #pragma unroll
    for (int i = 0; i < 3; i++) {
        int c = t + 256*i;
        out[base + c] = __float2bfloat16_rn(
            gate[base + c] * ((v[i] - mu) * rs) + skip[base + c]);
    }
}

// ---------------- pair bias ----------------
#define PPW 16
__global__ __launch_bounds__(256) void pairbias_k(const float* __restrict__ z,
                                                  float* __restrict__ out) {
    __shared__ float stage[8][PPW][17];
    int t = threadIdx.x, w = t >> 5, l = t & 31;
    int h = l & 15, half = l >> 4;
    const unsigned F = 0xffffffffu;

    ull wreg[32];
    {
        const float4* wrow = (const float4*)(&g_Wp[h*CZ + half*64]);
        #pragma unroll
        for (int j = 0; j < 16; j++) {
            float4 wv = wrow[j];
            wreg[2*j]   = pk2(wv.x, wv.y);
            wreg[2*j+1] = pk2(wv.z, wv.w);
        }
    }
    float Svr = g_Sv[h], Cvr = g_Cv[h];
    ll pbase = ((ll)blockIdx.x * 8 + w) * PPW;

    for (int pi = 0; pi < PPW; pi++) {
        ll p = pbase + pi;
        const float4* zr = (const float4*)(z + p * CZ);
        float4 zc = zr[l];
        float su = zc.x + zc.y + zc.z + zc.w;
        float sq = zc.x*zc.x + zc.y*zc.y + zc.z*zc.z + zc.w*zc.w;
        ull acc = 0;
        const float4* zh = zr + half * 16;
        #pragma unroll
        for (int j = 0; j < 16; j++) {
            float4 zv = zh[j];
            fma2(acc, pk2(zv.x, zv.y), wreg[2*j]);
            fma2(acc, pk2(zv.z, zv.w), wreg[2*j+1]);
        }
        #pragma unroll
        for (int o = 16; o; o >>= 1) {
            su += __shfl_xor_sync(F, su, o);
            sq += __shfl_xor_sync(F, sq, o);
        }
        float dsum = sum2(acc);
        float dfull = dsum + __shfl_xor_sync(F, dsum, 16);
        float mu = su * (1.f/CZ);
        float rs = rsqrtf(sq * (1.f/CZ) - mu*mu + 1e-5f);
        if (l < 16)
            stage[w][pi][l] = rs * (dfull - mu * Svr) + Cvr;
    }
    __syncwarp();
    #pragma unroll
    for (int hh = 0; hh < NH; hh++) {
        if (l < PPW)
            out[(ll)hh * NN + pbase + l] = stage[w][l][hh];
    }
}

// ---------------- softmax: fp32 logits -> bf16 probs ----------------
__global__ __launch_bounds__(256) void softmax_k(const float* __restrict__ lg,
                                                 __nv_bfloat16* __restrict__ pr) {
    ll base = (ll)blockIdx.x * NT;
    int t = threadIdx.x;
    float v0 = lg[base+t], v1 = lg[base+t+256], v2 = lg[base+t+512];
    float mx = blkreduce(fmaxf(v0, fmaxf(v1, v2)), true);
    float e0 = __expf(v0 - mx), e1 = __expf(v1 - mx), e2 = __expf(v2 - mx);
    float s = blkreduce(e0 + e1 + e2, false);
    float inv = 1.f / s;
    pr[base+t]     = __float2bfloat16_rn(e0*inv);
    pr[base+t+256] = __float2bfloat16_rn(e1*inv);
    pr[base+t+512] = __float2bfloat16_rn(e2*inv);
}

// ---------------- batched bf16 MMA GEMM, cp.async 4-stage ----------------
// flags: 1=BVEC 2=MATB(f32) 4=MULF32 8=ADDF32 16=ROWSC 32=STORET 64=MULBF16
struct ZArg {
    const __nv_bfloat16 *A, *W, *mulb;
    const float *bvec, *matb, *mulf, *addm, *rowsc;
    void *C;
    int lda, ldw, ldc, ldmb, ldmul, ldadd;
    int actf; float scale; int N, K;
};
struct ZPack { ZArg z[16]; };

template<int BMv, int OUTBF>
__global__ __launch_bounds__(256) void bgemm_k(ZPack P) {
    const ZArg za = P.z[blockIdx.z];
    constexpr int S = 4;
    __shared__ __align__(16) __nv_bfloat16 As[S][BMv][24];
    __shared__ __align__(16) __nv_bfloat16 Bs[S][64][24];
    int t = threadIdx.x;
    int m0 = blockIdx.y * BMv, n0 = blockIdx.x * 64;
    const int K = za.K, N = za.N;
    int niter = K >> 4;
    int nrem = N - n0;

    auto load_stage = [&](int st, int k0) {
        if (BMv == 128) {
            int row = t >> 1, kc = (t & 1) * 8;
            cpa16(su32(&As[st][row][kc]), za.A + (ll)(m0 + row) * za.lda + k0 + kc, 16);
            if (t < 128) {
                int brow = t >> 1, bkc = (t & 1) * 8;
                int bytes = (brow < nrem) ? 16 : 0;
                const __nv_bfloat16* src = (bytes ?
                    za.W + (ll)(n0 + brow) * za.ldw + k0 + bkc : za.W);
                cpa16(su32(&Bs[st][brow][bkc]), src, bytes);
            }
        } else {
            if (t < 128) {
                int row = t >> 1, kc = (t & 1) * 8;
                cpa16(su32(&As[st][row][kc]), za.A + (ll)(m0 + row) * za.lda + k0 + kc, 16);
            } else {
                int brow = (t - 128) >> 1, bkc = (t & 1) * 8;
                int bytes = (brow < nrem) ? 16 : 0;
                const __nv_bfloat16* src = (bytes ?
                    za.W + (ll)(n0 + brow) * za.ldw + k0 + bkc : za.W);
                cpa16(su32(&Bs[st][brow][bkc]), src, bytes);
            }
        }
    };

    #pragma unroll
    for (int i = 0; i < S-1; i++) {
        if (i < niter) load_stage(i, i * 16);
        cpcommit();
    }

    int wid = t >> 5, lane = t & 31;
    int lr = lane >> 2, lc = lane & 3;
    constexpr int NTW = (BMv == 128) ? 4 : 2;
    int wm = (BMv == 128) ? (wid & 3) * 32 : (wid & 1) * 32;
    int wn = (BMv == 128) ? (wid >> 2) * 32 : (wid >> 1) * 16;

    float acc[2][NTW][4] = {};

    for (int it = 0; it < niter; it++) {
        cpwait<S-2>();
        __syncthreads();
        int pf = it + S - 1;
        if (pf < niter) load_stage(pf & 3, pf * 16);
        cpcommit();
        int st = it & 3;

        unsigned afr[2][4], bfr[NTW][2];
        #pragma unroll
        for (int mt = 0; mt < 2; mt++) {
            int r0 = wm + 16*mt + lr;
            afr[mt][0] = *(const unsigned*)&As[st][r0    ][2*lc];
            afr[mt][1] = *(const unsigned*)&As[st][r0 + 8][2*lc];
            afr[mt][2] = *(const unsigned*)&As[st][r0    ][2*lc + 8];
            afr[mt][3] = *(const unsigned*)&As[st][r0 + 8][2*lc + 8];
        }
        #pragma unroll
        for (int nt = 0; nt < NTW; nt++) {
            int c0 = wn + 8*nt + lr;
            bfr[nt][0] = *(const unsigned*)&Bs[st][c0][2*lc];
            bfr[nt][1] = *(const unsigned*)&Bs[st][c0][2*lc + 8];
        }
        #pragma unroll
        for (int mt = 0; mt < 2; mt++)
            #pragma unroll
            for (int nt = 0; nt < NTW; nt++) {
                float* cc = acc[mt][nt];
                asm volatile(
                    "mma.sync.aligned.m16n8k16.row.col.f32.bf16.bf16.f32 "
                    "{%0,%1,%2,%3}, {%4,%5,%6,%7}, {%8,%9}, {%0,%1,%2,%3};\n"
                    : "+f"(cc[0]), "+f"(cc[1]), "+f"(cc[2]), "+f"(cc[3])
                    : "r"(afr[mt][0]), "r"(afr[mt][1]), "r"(afr[mt][2]), "r"(afr[mt][3]),
                      "r"(bfr[nt][0]), "r"(bfr[nt][1]));
            }
        __syncthreads();
    }

    int act = za.actf & 15, flg = za.actf >> 4;
    auto ep = [&](int m, int n, float v) {
        if (n >= N) return;
        v *= za.scale;
        if (flg & 1)  v += za.bvec[n];
        if (flg & 2)  v += za.matb[(ll)m * za.ldmb + n];
        if (act == 1) v = 1.f / (1.f + __expf(-v));
        else if (act == 2) v = v / (1.f + __expf(-v));
        if (flg & 4)  v *= za.mulf[(ll)m * za.ldmul + n];
        if (flg & 64) v *= __bfloat162float(za.mulb[(ll)m * za.ldmul + n]);
        if (flg & 16) v *= za.rowsc[m];
        if (flg & 8)  v += za.addm[(ll)m * za.ldadd + n];
        ll idx = (flg & 32) ? (ll)n * za.ldc + m : (ll)m * za.ldc + n;
        if (OUTBF) ((__nv_bfloat16*)za.C)[idx] = __float2bfloat16_rn(v);
        else       ((float*)za.C)[idx] = v;
    };
    #pragma unroll
    for (int mt = 0; mt < 2; mt++)
        #pragma unroll
        for (int nt = 0; nt < NTW; nt++) {
            int mrow = m0 + wm + 16*mt + lr;
            int ncol = n0 + wn + 8*nt + 2*lc;
            float* cc = acc[mt][nt];
            ep(mrow,     ncol,     cc[0]);
            ep(mrow,     ncol + 1, cc[1]);
            ep(mrow + 8, ncol,     cc[2]);
            ep(mrow + 8, ncol + 1, cc[3]);
        }
}

// ---------------- host orchestration ----------------
#define SYM(p, ty, name) do { void* _t; cudaGetSymbolAddress(&_t, name); p = (ty*)_t; } while (0)

static ZArg mk(const __nv_bfloat16* A, int lda, const __nv_bfloat16* W, int ldw,
               void* C, int ldc, int N, int K, float scale, int act, int flg,
               const float* bvec = nullptr,
               const float* matb = nullptr, int ldmb = 0,
               const float* mulf = nullptr, const __nv_bfloat16* mulb = nullptr, int ldmul = 0,
               const float* addm = nullptr, int ldadd = 0,
               const float* rowsc = nullptr) {
    ZArg z;
    z.A = A; z.W = W; z.C = C; z.bvec = bvec; z.matb = matb;
    z.mulf = mulf; z.mulb = mulb; z.addm = addm; z.rowsc = rowsc;
    z.lda = lda; z.ldw = ldw; z.ldc = ldc; z.ldmb = ldmb; z.ldmul = ldmul; z.ldadd = ldadd;
    z.actf = act | (flg << 4); z.scale = scale; z.N = N; z.K = K;
    return z;
}

extern "C" void kernel_launch(void* const* d_in, const int* in_sizes, int n_in,
                              void* d_out, int out_size) {
    const float* a    = (const float*)d_in[0];
    const float* s    = (const float*)d_in[1];
    const float* z    = (const float*)d_in[2];
    const int*   mask = (const int*)  d_in[3];
    const float* a_slng  = (const float*)d_in[4];
    const float* a_gw    = (const float*)d_in[5];
    const float* a_gb    = (const float*)d_in[6];
    const float* a_sw    = (const float*)d_in[7];
    const float* wq   = (const float*)d_in[8];
    const float* bq   = (const float*)d_in[9];
    const float* wk   = (const float*)d_in[10];
    const float* wv   = (const float*)d_in[11];
    const float* zlng = (const float*)d_in[12];
    const float* zlnb = (const float*)d_in[13];
    const float* wb   = (const float*)d_in[14];
    const float* wg   = (const float*)d_in[15];
    const float* wo   = (const float*)d_in[16];
    const float* aogw = (const float*)d_in[17];
    const float* aogb = (const float*)d_in[18];
    const float* t_slng = (const float*)d_in[19];
    const float* t_gw   = (const float*)d_in[20];
    const float* t_gb   = (const float*)d_in[21];
    const float* t_sw   = (const float*)d_in[22];
    const float* w1   = (const float*)d_in[23];
    const float* w2   = (const float*)d_in[24];
    const float* two  = (const float*)d_in[25];
    const float* togw = (const float*)d_in[26];
    const float* togb = (const float*)d_in[27];
    float* out = (float*)d_out;

    float *gateA,*skipA,*outGA,*gateT,*skipT,*outGT,*logits,*anew,*maskb,*maskf;
    SYM(gateA, float, g_gateA); SYM(skipA, float, g_skipA); SYM(outGA, float, g_outGA);
    SYM(gateT, float, g_gateT); SYM(skipT, float, g_skipT); SYM(outGT, float, g_outGT);
    SYM(logits, float, g_logits); SYM(anew, float, g_anew);
    SYM(maskb, float, g_maskb); SYM(maskf, float, g_maskf);

    __nv_bfloat16 *slnA,*slnT,*sbf,*aln,*qb,*kb,*vT,*gb,*probs,*og,*h1,*hid,*wpool;
    SYM(slnA, __nv_bfloat16, b_slnA); SYM(slnT, __nv_bfloat16, b_slnT);
    SYM(sbf, __nv_bfloat16, b_s);     SYM(aln, __nv_bfloat16, b_aln);
    SYM(qb, __nv_bfloat16, b_q);      SYM(kb, __nv_bfloat16, b_k);
    SYM(vT, __nv_bfloat16, b_vT);     SYM(gb, __nv_bfloat16, b_g);
    SYM(probs, __nv_bfloat16, b_probs); SYM(og, __nv_bfloat16, b_og);
    SYM(h1, __nv_bfloat16, b_h1);     SYM(hid, __nv_bfloat16, b_hid);
    SYM(wpool, __nv_bfloat16, b_wpool);

    // weight pool offsets
    const ll GSZ = (ll)CS*CA, PSZ = (ll)CA*CA, WSZ = (ll)CA*1536;
    __nv_bfloat16 *agwT = wpool,        *aswT = agwT + GSZ, *aogwT = aswT + GSZ;
    __nv_bfloat16 *tgwT = aogwT + GSZ,  *tswT = tgwT + GSZ, *togwT = tswT + GSZ;
    __nv_bfloat16 *wqT = togwT + GSZ, *wkT = wqT + PSZ, *wvT = wkT + PSZ;
    __nv_bfloat16 *wgT = wvT + PSZ, *woT = wgT + PSZ;
    __nv_bfloat16 *w1T = woT + PSZ, *w2T = w1T + WSZ, *twoT = w2T + WSZ;

    prep_k<<<1, 256>>>(mask, zlng, zlnb, wb);
    {
        TPack TP;
        TP.t[0]  = { a_gw, agwT, CS, CA };
        TP.t[1]  = { a_sw, aswT, CS, CA };
        TP.t[2]  = { aogw, aogwT, CS, CA };
        TP.t[3]  = { t_gw, tgwT, CS, CA };
        TP.t[4]  = { t_sw, tswT, CS, CA };
        TP.t[5]  = { togw, togwT, CS, CA };
        TP.t[6]  = { wq, wqT, CA, CA };
        TP.t[7]  = { wk, wkT, CA, CA };
        TP.t[8]  = { wv, wvT, CA, CA };
        TP.t[9]  = { wg, wgT, CA, CA };
        TP.t[10] = { wo, woT, CA, CA };
        TP.t[11] = { w1, w1T, CA, 1536 };
        TP.t[12] = { w2, w2T, CA, 1536 };
        TP.t[13] = { two, twoT, 1536, CA };
        trans_k<<<dim3(48, 48, 14), 256>>>(TP);
    }
    lns_k<<<NT, 128>>>(s, a_slng, t_slng);

    // ---- batch 1: six s-conditioned gate/skip GEMMs (K=384) -> fp32 ----
    {
        ZPack P;
        P.z[0] = mk(slnA, CS, agwT,  CS, gateA, CA, CA, CS, 1.f, 1, 1, a_gb);
        P.z[1] = mk(slnA, CS, aswT,  CS, skipA, CA, CA, CS, 1.f, 0, 0);
        P.z[2] = mk(sbf,  CS, aogwT, CS, outGA, CA, CA, CS, 1.f, 1, 1, aogb);
        P.z[3] = mk(slnT, CS, tgwT,  CS, gateT, CA, CA, CS, 1.f, 1, 1, t_gb);
        P.z[4] = mk(slnT, CS, tswT,  CS, skipT, CA, CA, CS, 1.f, 0, 0);
        P.z[5] = mk(sbf,  CS, togwT, CS, outGT, CA, CA, CS, 1.f, 1, 1, togb);
        bgemm_k<128,0><<<dim3(12,6,6), 256>>>(P);
    }

    adaln_k<<<NT, 256>>>(a, gateA, skipA, aln);

    // ---- batch 2: QKVG projections (K=768) -> bf16 ----
    {
        ZPack P;
        P.z[0] = mk(aln, CA, wqT, CA, qb, CA, CA, CA, 1.f, 0, 1, bq);
        P.z[1] = mk(aln, CA, wkT, CA, kb, CA, CA, CA, 1.f, 0, 0);
        P.z[2] = mk(aln, CA, wvT, CA, vT, NT, CA, CA, 1.f, 0, 32);
        P.z[3] = mk(aln, CA, wgT, CA, gb, CA, CA, CA, 1.f, 1, 0);
        bgemm_k<128,1><<<dim3(12,6,4), 256>>>(P);
    }

    pairbias_k<<<NN/(8*PPW), 256>>>(z, logits);

    // ---- batch 3: logits per head (K=48), fp32 out, bias+mask fused ----
    {
        ZPack P;
        for (int h = 0; h < NH; h++)
            P.z[h] = mk(qb + 48*h, CA, kb + 48*h, CA,
                        logits + (ll)NN*h, NT, NT, CH, 0.14433756729740643f,
                        0, 1 | 2, maskb, logits + (ll)NN*h, NT);
        bgemm_k<128,0><<<dim3(12,6,16), 256>>>(P);
    }

    softmax_k<<<NH*NT, 256>>>(logits, probs);

    // ---- batch 4: AV per head (K=768), gated by g -> bf16 og ----
    {
        ZPack P;
        for (int h = 0; h < NH; h++)
            P.z[h] = mk(probs + (ll)NN*h, NT, vT + (ll)48*NT*h, NT,
                        og + 48*h, CA, CH, NT, 1.f,
                        0, 64, nullptr, nullptr, 0, nullptr, gb + 48*h, CA);
        bgemm_k<64,1><<<dim3(1,12,16), 256>>>(P);
    }

    // ---- a_new = a + outGA * (og @ wo) -> fp32 ----
    {
        ZPack P;
        P.z[0] = mk(og, CA, woT, CA, anew, CA, CA, CA, 1.f,
                    0, 4 | 8, nullptr, nullptr, 0, outGA, nullptr, CA, a, CA);
        bgemm_k<64,0><<<dim3(12,12,1), 256>>>(P);
    }

    adaln_k<<<NT, 256>>>(anew, gateT, skipT, aln);

    // ---- SwiGLU (K=768, N=1536) ----
    {
        ZPack P;
        P.z[0] = mk(aln, CA, w1T, CA, h1, 1536, 1536, CA, 1.f, 2, 0);
        bgemm_k<128,1><<<dim3(24,6,1), 256>>>(P);
    }
    {
        ZPack P;
        P.z[0] = mk(aln, CA, w2T, CA, hid, 1536, 1536, CA, 1.f,
                    0, 64, nullptr, nullptr, 0, nullptr, h1, 1536);
        bgemm_k<128,1><<<dim3(24,6,1), 256>>>(P);
    }

    // ---- out = a_new + maskf * outGT * (hid @ tr_wo) -> fp32 ----
    {
        ZPack P;
        P.z[0] = mk(hid, 1536, twoT, 1536, out, CA, CA, 1536, 1.f,
                    0, 4 | 8 | 16, nullptr, nullptr, 0, outGT, nullptr, CA,
                    anew, CA, maskf);
        bgemm_k<64,0><<<dim3(12,12,1), 256>>>(P);
    }
}

// round 11
// speedup vs baseline: 2.2887x; 1.0276x over previous
#include <cuda_runtime.h>
#include <cuda_bf16.h>
#include <math.h>

typedef long long ll;
typedef unsigned long long ull;

#define NT 768
#define CA 768
#define CS 384
#define CZ 128
#define NH 16
#define CH 48
#define NN (768*768)

// ---------------- fp32 scratch ----------------
__device__ float g_gateA[NT*CA], g_skipA[NT*CA], g_outGA[NT*CA];
__device__ float g_gateT[NT*CA], g_skipT[NT*CA], g_outGT[NT*CA];
__device__ float g_logits[NH*NN];
__device__ float g_anew[NT*CA];
__device__ float g_Wp[NH*CZ], g_Sv[NH], g_Cv[NH], g_maskb[NT], g_maskf[NT];

// ---------------- bf16 scratch ----------------
__device__ __nv_bfloat16 b_slnA[NT*CS], b_slnT[NT*CS], b_s[NT*CS];
__device__ __nv_bfloat16 b_aln[NT*CA], b_q[NT*CA], b_k[NT*CA];
__device__ __nv_bfloat16 b_vT[CA*NT], b_g[NT*CA];
__device__ __nv_bfloat16 b_probs[NH*NN];
__device__ __nv_bfloat16 b_og[NT*CA], b_h1[NT*1536], b_hid[NT*1536];
__device__ __nv_bfloat16 b_wpool[8257536];

// ---------------- helpers ----------------
__device__ __forceinline__ ull pk2(float x, float y) {
    ull r; asm("mov.b64 %0, {%1, %2};" : "=l"(r) : "f"(x), "f"(y)); return r;
}
__device__ __forceinline__ void fma2(ull &d, ull a, ull b) {
    asm("fma.rn.f32x2 %0, %1, %2, %0;" : "+l"(d) : "l"(a), "l"(b));
}
__device__ __forceinline__ float sum2(ull v) {
    float x, y; asm("mov.b64 {%0, %1}, %2;" : "=f"(x), "=f"(y) : "l"(v));
    return x + y;
}
__device__ __forceinline__ unsigned su32(const void* p) {
    return (unsigned)__cvta_generic_to_shared(p);
}
__device__ __forceinline__ void cpa16(unsigned dst, const void* src, int bytes) {
    asm volatile("cp.async.ca.shared.global [%0], [%1], 16, %2;\n"
                 :: "r"(dst), "l"(src), "r"(bytes));
}
__device__ __forceinline__ void cpcommit() { asm volatile("cp.async.commit_group;\n"); }
template<int Ng> __device__ __forceinline__ void cpwait() {
    asm volatile("cp.async.wait_group %0;\n" :: "n"(Ng));
}
__device__ __forceinline__ void ldsm4(unsigned &r0, unsigned &r1, unsigned &r2,
                                      unsigned &r3, unsigned addr) {
    asm volatile("ldmatrix.sync.aligned.m8n8.x4.shared.b16 {%0,%1,%2,%3}, [%4];"
                 : "=r"(r0), "=r"(r1), "=r"(r2), "=r"(r3) : "r"(addr));
}

__device__ __forceinline__ float blkreduce(float v, bool domax) {
    __shared__ float sm[32];
    const unsigned F = 0xffffffffu;
    #pragma unroll
    for (int o = 16; o; o >>= 1) {
        float u = __shfl_xor_sync(F, v, o);
        v = domax ? fmaxf(v, u) : v + u;
    }
    __syncthreads();
    if ((threadIdx.x & 31) == 0) sm[threadIdx.x >> 5] = v;
    __syncthreads();
    int nw = blockDim.x >> 5;
    if (threadIdx.x < 32) {
        float u = (threadIdx.x < nw) ? sm[threadIdx.x] : (domax ? -3.4e38f : 0.f);
        #pragma unroll
        for (int o = 16; o; o >>= 1) {
            float w = __shfl_xor_sync(F, u, o);
            u = domax ? fmaxf(u, w) : u + w;
        }
        if (threadIdx.x == 0) sm[0] = u;
    }
    __syncthreads();
    return sm[0];
}

// ---------------- prep: mask, folded pair-bias weights ----------------
__global__ void prep_k(const int* __restrict__ mask, const float* __restrict__ zg,
                       const float* __restrict__ zb, const float* __restrict__ wb) {
    int t = threadIdx.x;
    for (int i = t; i < NT; i += 256) {
        float m = (float)mask[i];
        g_maskf[i] = m;
        g_maskb[i] = (m - 1.f) * 1e9f;
    }
    for (int i = t; i < NH*CZ; i += 256) {
        int h = i >> 7, c = i & 127;
        g_Wp[i] = zg[c] * wb[c*NH + h];
    }
    if (t < NH) {
        float s = 0.f, cs = 0.f;
        for (int c = 0; c < CZ; c++) {
            s  += zg[c] * wb[c*NH + t];
            cs += zb[c] * wb[c*NH + t];
        }
        g_Sv[t] = s; g_Cv[t] = cs;
    }
}

// ---------------- weight transpose + bf16 convert ----------------
struct TArg { const float* src; __nv_bfloat16* dst; int K; int N; };
struct TPack { TArg t[14]; };

__global__ __launch_bounds__(256) void trans_k(TPack P) {
    TArg ta = P.t[blockIdx.z];
    int x0 = blockIdx.x * 32, y0 = blockIdx.y * 32;
    if (x0 >= ta.N || y0 >= ta.K) return;
    __shared__ float tile[32][33];
    int tx = threadIdx.x & 31, ty = threadIdx.x >> 5;  // 32x8
    #pragma unroll
    for (int i = 0; i < 32; i += 8) {
        int k = y0 + ty + i, n = x0 + tx;
        if (k < ta.K && n < ta.N) tile[ty + i][tx] = ta.src[(ll)k * ta.N + n];
    }
    __syncthreads();
    #pragma unroll
    for (int i = 0; i < 32; i += 8) {
        int n = x0 + ty + i, k = y0 + tx;
        if (n < ta.N && k < ta.K)
            ta.dst[(ll)n * ta.K + k] = __float2bfloat16_rn(tile[tx][ty + i]);
    }
}

// ---------------- LN(s) dual scale + bf16 s copy ----------------
__global__ __launch_bounds__(128) void lns_k(const float* __restrict__ s,
                                             const float* __restrict__ gA,
                                             const float* __restrict__ gT) {
    int r = blockIdx.x, t = threadIdx.x;
    const float* x = s + (ll)r * CS;
    float v[3]; float su = 0.f, q = 0.f;
    #pragma unroll
    for (int i = 0; i < 3; i++) { v[i] = x[t + 128*i]; su += v[i]; q += v[i]*v[i]; }
    su = blkreduce(su, false);
    q  = blkreduce(q, false);
    float mu = su * (1.f/CS);
    float rs = rsqrtf(q * (1.f/CS) - mu*mu + 1e-5f);
    ll base = (ll)r * CS;
    #pragma unroll
    for (int i = 0; i < 3; i++) {
        int c = t + 128*i;
        float xh = (v[i] - mu) * rs;
        b_slnA[base + c] = __float2bfloat16_rn(xh * gA[c]);
        b_slnT[base + c] = __float2bfloat16_rn(xh * gT[c]);
        b_s[base + c]    = __float2bfloat16_rn(v[i]);
    }
}

// ---------------- AdaLN combine -> bf16 ----------------
__global__ __launch_bounds__(256) void adaln_k(const float* __restrict__ a,
                                               const float* __restrict__ gate,
                                               const float* __restrict__ skip,
                                               __nv_bfloat16* __restrict__ out) {
    int r = blockIdx.x, t = threadIdx.x;
    const float* x = a + (ll)r * CA;
    float v[3]; float su = 0.f, q = 0.f;
    #pragma unroll
    for (int i = 0; i < 3; i++) { v[i] = x[t + 256*i]; su += v[i]; q += v[i]*v[i]; }
    su = blkreduce(su, false);
    q  = blkreduce(q, false);
    float mu = su * (1.f/CA);
    float rs = rsqrtf(q * (1.f/CA) - mu*mu + 1e-5f);
    ll base = (ll)r * CA;
    #pragma unroll
    for (int i = 0; i < 3; i++) {
        int c = t + 256*i;
        out[base + c] = __float2bfloat16_rn(
            gate[base + c] * ((v[i] - mu) * rs) + skip[base + c]);
    }
}

// ---------------- pair bias ----------------
#define PPW 16
__global__ __launch_bounds__(256) void pairbias_k(const float* __restrict__ z,
                                                  float* __restrict__ out) {
    __shared__ float stage[8][PPW][17];
    int t = threadIdx.x, w = t >> 5, l = t & 31;
    int h = l & 15, half = l >> 4;
    const unsigned F = 0xffffffffu;

    ull wreg[32];
    {
        const float4* wrow = (const float4*)(&g_Wp[h*CZ + half*64]);
        #pragma unroll
        for (int j = 0; j < 16; j++) {
            float4 wv = wrow[j];
            wreg[2*j]   = pk2(wv.x, wv.y);
            wreg[2*j+1] = pk2(wv.z, wv.w);
        }
    }
    float Svr = g_Sv[h], Cvr = g_Cv[h];
    ll pbase = ((ll)blockIdx.x * 8 + w) * PPW;

    for (int pi = 0; pi < PPW; pi++) {
        ll p = pbase + pi;
        const float4* zr = (const float4*)(z + p * CZ);
        float4 zc = zr[l];
        float su = zc.x + zc.y + zc.z + zc.w;
        float sq = zc.x*zc.x + zc.y*zc.y + zc.z*zc.z + zc.w*zc.w;
        ull acc = 0;
        const float4* zh = zr + half * 16;
        #pragma unroll
        for (int j = 0; j < 16; j++) {
            float4 zv = zh[j];
            fma2(acc, pk2(zv.x, zv.y), wreg[2*j]);
            fma2(acc, pk2(zv.z, zv.w), wreg[2*j+1]);
        }
        #pragma unroll
        for (int o = 16; o; o >>= 1) {
            su += __shfl_xor_sync(F, su, o);
            sq += __shfl_xor_sync(F, sq, o);
        }
        float dsum = sum2(acc);
        float dfull = dsum + __shfl_xor_sync(F, dsum, 16);
        float mu = su * (1.f/CZ);
        float rs = rsqrtf(sq * (1.f/CZ) - mu*mu + 1e-5f);
        if (l < 16)
            stage[w][pi][l] = rs * (dfull - mu * Svr) + Cvr;
    }
    __syncwarp();
    #pragma unroll
    for (int hh = 0; hh < NH; hh++) {
        if (l < PPW)
            out[(ll)hh * NN + pbase + l] = stage[w][l][hh];
    }
}

// ---------------- softmax: fp32 logits -> bf16 probs ----------------
__global__ __launch_bounds__(256) void softmax_k(const float* __restrict__ lg,
                                                 __nv_bfloat16* __restrict__ pr) {
    ll base = (ll)blockIdx.x * NT;
    int t = threadIdx.x;
    float v0 = lg[base+t], v1 = lg[base+t+256], v2 = lg[base+t+512];
    float mx = blkreduce(fmaxf(v0, fmaxf(v1, v2)), true);
    float e0 = __expf(v0 - mx), e1 = __expf(v1 - mx), e2 = __expf(v2 - mx);
    float s = blkreduce(e0 + e1 + e2, false);
    float inv = 1.f / s;
    pr[base+t]     = __float2bfloat16_rn(e0*inv);
    pr[base+t+256] = __float2bfloat16_rn(e1*inv);
    pr[base+t+512] = __float2bfloat16_rn(e2*inv);
}

// ---------------- batched bf16 MMA GEMM, cp.async 4-stage, ldmatrix ----------------
// flags: 1=BVEC 2=MATB(f32) 4=MULF32 8=ADDF32 16=ROWSC 32=STORET 64=MULBF16
struct ZArg {
    const __nv_bfloat16 *A, *W, *mulb;
    const float *bvec, *matb, *mulf, *addm, *rowsc;
    void *C;
    int lda, ldw, ldc, ldmb, ldmul, ldadd;
    int actf; float scale; int N, K;
};
struct ZPack { ZArg z[16]; };

template<int BMv, int OUTBF>
__global__ __launch_bounds__(256) void bgemm_k(ZPack P) {
    const ZArg za = P.z[blockIdx.z];
    constexpr int S = 4;
    __shared__ __align__(16) __nv_bfloat16 As[S][BMv][24];
    __shared__ __align__(16) __nv_bfloat16 Bs[S][64][24];
    int t = threadIdx.x;
    int m0 = blockIdx.y * BMv, n0 = blockIdx.x * 64;
    const int K = za.K, N = za.N;
    int niter = K >> 4;
    int nrem = N - n0;

    auto load_stage = [&](int st, int k0) {
        if (BMv == 128) {
            int row = t >> 1, kc = (t & 1) * 8;
            cpa16(su32(&As[st][row][kc]), za.A + (ll)(m0 + row) * za.lda + k0 + kc, 16);
            if (t < 128) {
                int brow = t >> 1, bkc = (t & 1) * 8;
                int bytes = (brow < nrem) ? 16 : 0;
                const __nv_bfloat16* src = (bytes ?
                    za.W + (ll)(n0 + brow) * za.ldw + k0 + bkc : za.W);
                cpa16(su32(&Bs[st][brow][bkc]), src, bytes);
            }
        } else {
            if (t < 128) {
                int row = t >> 1, kc = (t & 1) * 8;
                cpa16(su32(&As[st][row][kc]), za.A + (ll)(m0 + row) * za.lda + k0 + kc, 16);
            } else {
                int brow = (t - 128) >> 1, bkc = (t & 1) * 8;
                int bytes = (brow < nrem) ? 16 : 0;
                const __nv_bfloat16* src = (bytes ?
                    za.W + (ll)(n0 + brow) * za.ldw + k0 + bkc : za.W);
                cpa16(su32(&Bs[st][brow][bkc]), src, bytes);
            }
        }
    };

    #pragma unroll
    for (int i = 0; i < S-1; i++) {
        if (i < niter) load_stage(i, i * 16);
        cpcommit();
    }

    int wid = t >> 5, lane = t & 31;
    int lr = lane >> 2, lc = lane & 3;
    constexpr int NTW = (BMv == 128) ? 4 : 2;
    int wm = (BMv == 128) ? (wid & 3) * 32 : (wid & 1) * 32;
    int wn = (BMv == 128) ? (wid >> 2) * 32 : (wid >> 1) * 16;

    // ldmatrix lane addresses (stage 0); stage strides in bytes
    constexpr unsigned ASTG = BMv * 24 * 2;
    constexpr unsigned BSTG = 64 * 24 * 2;
    unsigned aAddr, bAddr;
    {
        int arow = wm + (lane & 15);
        int acol = (lane >> 4) * 8;
        aAddr = su32(&As[0][0][0]) + (unsigned)(arow * 24 + acol) * 2;
        int brow = wn + ((lane >> 4) * 8) + (lane & 7);
        int bcol = ((lane >> 3) & 1) * 8;
        bAddr = su32(&Bs[0][0][0]) + (unsigned)(brow * 24 + bcol) * 2;
    }

    float acc[2][NTW][4] = {};

    for (int it = 0; it < niter; it++) {
        cpwait<S-2>();
        __syncthreads();
        int pf = it + S - 1;
        if (pf < niter) load_stage(pf & 3, pf * 16);
        cpcommit();
        int st = it & 3;
        unsigned sA = aAddr + st * ASTG;
        unsigned sB = bAddr + st * BSTG;

        unsigned afr[2][4], bfr[NTW][2];
        #pragma unroll
        for (int mt = 0; mt < 2; mt++)
            ldsm4(afr[mt][0], afr[mt][1], afr[mt][2], afr[mt][3], sA + mt * 768u);
        #pragma unroll
        for (int np = 0; np < NTW/2; np++)
            ldsm4(bfr[2*np][0], bfr[2*np][1], bfr[2*np+1][0], bfr[2*np+1][1],
                  sB + np * 768u);
        #pragma unroll
        for (int mt = 0; mt < 2; mt++)
            #pragma unroll
            for (int nt = 0; nt < NTW; nt++) {
                float* cc = acc[mt][nt];
                asm volatile(
                    "mma.sync.aligned.m16n8k16.row.col.f32.bf16.bf16.f32 "
                    "{%0,%1,%2,%3}, {%4,%5,%6,%7}, {%8,%9}, {%0,%1,%2,%3};\n"
                    : "+f"(cc[0]), "+f"(cc[1]), "+f"(cc[2]), "+f"(cc[3])
                    : "r"(afr[mt][0]), "r"(afr[mt][1]), "r"(afr[mt][2]), "r"(afr[mt][3]),
                      "r"(bfr[nt][0]), "r"(bfr[nt][1]));
            }
    }

    int act = za.actf & 15, flg = za.actf >> 4;
    auto ep = [&](int m, int n, float v) {
        if (n >= N) return;
        v *= za.scale;
        if (flg & 1)  v += za.bvec[n];
        if (flg & 2)  v += za.matb[(ll)m * za.ldmb + n];
        if (act == 1) v = 1.f / (1.f + __expf(-v));
        else if (act == 2) v = v / (1.f + __expf(-v));
        if (flg & 4)  v *= za.mulf[(ll)m * za.ldmul + n];
        if (flg & 64) v *= __bfloat162float(za.mulb[(ll)m * za.ldmul + n]);
        if (flg & 16) v *= za.rowsc[m];
        if (flg & 8)  v += za.addm[(ll)m * za.ldadd + n];
        ll idx = (flg & 32) ? (ll)n * za.ldc + m : (ll)m * za.ldc + n;
        if (OUTBF) ((__nv_bfloat16*)za.C)[idx] = __float2bfloat16_rn(v);
        else       ((float*)za.C)[idx] = v;
    };
    #pragma unroll
    for (int mt = 0; mt < 2; mt++)
        #pragma unroll
        for (int nt = 0; nt < NTW; nt++) {
            int mrow = m0 + wm + 16*mt + lr;
            int ncol = n0 + wn + 8*nt + 2*lc;
            float* cc = acc[mt][nt];
            ep(mrow,     ncol,     cc[0]);
            ep(mrow,     ncol + 1, cc[1]);
            ep(mrow + 8, ncol,     cc[2]);
            ep(mrow + 8, ncol + 1, cc[3]);
        }
}

// ---------------- host orchestration ----------------
#define SYM(p, ty, name) do { void* _t; cudaGetSymbolAddress(&_t, name); p = (ty*)_t; } while (0)

static ZArg mk(const __nv_bfloat16* A, int lda, const __nv_bfloat16* W, int ldw,
               void* C, int ldc, int N, int K, float scale, int act, int flg,
               const float* bvec = nullptr,
               const float* matb = nullptr, int ldmb = 0,
               const float* mulf = nullptr, const __nv_bfloat16* mulb = nullptr, int ldmul = 0,
               const float* addm = nullptr, int ldadd = 0,
               const float* rowsc = nullptr) {
    ZArg z;
    z.A = A; z.W = W; z.C = C; z.bvec = bvec; z.matb = matb;
    z.mulf = mulf; z.mulb = mulb; z.addm = addm; z.rowsc = rowsc;
    z.lda = lda; z.ldw = ldw; z.ldc = ldc; z.ldmb = ldmb; z.ldmul = ldmul; z.ldadd = ldadd;
    z.actf = act | (flg << 4); z.scale = scale; z.N = N; z.K = K;
    return z;
}

extern "C" void kernel_launch(void* const* d_in, const int* in_sizes, int n_in,
                              void* d_out, int out_size) {
    const float* a    = (const float*)d_in[0];
    const float* s    = (const float*)d_in[1];
    const float* z    = (const float*)d_in[2];
    const int*   mask = (const int*)  d_in[3];
    const float* a_slng  = (const float*)d_in[4];
    const float* a_gw    = (const float*)d_in[5];
    const float* a_gb    = (const float*)d_in[6];
    const float* a_sw    = (const float*)d_in[7];
    const float* wq   = (const float*)d_in[8];
    const float* bq   = (const float*)d_in[9];
    const float* wk   = (const float*)d_in[10];
    const float* wv   = (const float*)d_in[11];
    const float* zlng = (const float*)d_in[12];
    const float* zlnb = (const float*)d_in[13];
    const float* wb   = (const float*)d_in[14];
    const float* wg   = (const float*)d_in[15];
    const float* wo   = (const float*)d_in[16];
    const float* aogw = (const float*)d_in[17];
    const float* aogb = (const float*)d_in[18];
    const float* t_slng = (const float*)d_in[19];
    const float* t_gw   = (const float*)d_in[20];
    const float* t_gb   = (const float*)d_in[21];
    const float* t_sw   = (const float*)d_in[22];
    const float* w1   = (const float*)d_in[23];
    const float* w2   = (const float*)d_in[24];
    const float* two  = (const float*)d_in[25];
    const float* togw = (const float*)d_in[26];
    const float* togb = (const float*)d_in[27];
    float* out = (float*)d_out;

    float *gateA,*skipA,*outGA,*gateT,*skipT,*outGT,*logits,*anew,*maskb,*maskf;
    SYM(gateA, float, g_gateA); SYM(skipA, float, g_skipA); SYM(outGA, float, g_outGA);
    SYM(gateT, float, g_gateT); SYM(skipT, float, g_skipT); SYM(outGT, float, g_outGT);
    SYM(logits, float, g_logits); SYM(anew, float, g_anew);
    SYM(maskb, float, g_maskb); SYM(maskf, float, g_maskf);

    __nv_bfloat16 *slnA,*slnT,*sbf,*aln,*qb,*kb,*vT,*gb,*probs,*og,*h1,*hid,*wpool;
    SYM(slnA, __nv_bfloat16, b_slnA); SYM(slnT, __nv_bfloat16, b_slnT);
    SYM(sbf, __nv_bfloat16, b_s);     SYM(aln, __nv_bfloat16, b_aln);
    SYM(qb, __nv_bfloat16, b_q);      SYM(kb, __nv_bfloat16, b_k);
    SYM(vT, __nv_bfloat16, b_vT);     SYM(gb, __nv_bfloat16, b_g);
    SYM(probs, __nv_bfloat16, b_probs); SYM(og, __nv_bfloat16, b_og);
    SYM(h1, __nv_bfloat16, b_h1);     SYM(hid, __nv_bfloat16, b_hid);
    SYM(wpool, __nv_bfloat16, b_wpool);

    // weight pool offsets
    const ll GSZ = (ll)CS*CA, PSZ = (ll)CA*CA, WSZ = (ll)CA*1536;
    __nv_bfloat16 *agwT = wpool,        *aswT = agwT + GSZ, *aogwT = aswT + GSZ;
    __nv_bfloat16 *tgwT = aogwT + GSZ,  *tswT = tgwT + GSZ, *togwT = tswT + GSZ;
    __nv_bfloat16 *wqT = togwT + GSZ, *wkT = wqT + PSZ, *wvT = wkT + PSZ;
    __nv_bfloat16 *wgT = wvT + PSZ, *woT = wgT + PSZ;
    __nv_bfloat16 *w1T = woT + PSZ, *w2T = w1T + WSZ, *twoT = w2T + WSZ;

    prep_k<<<1, 256>>>(mask, zlng, zlnb, wb);
    {
        TPack TP;
        TP.t[0]  = { a_gw, agwT, CS, CA };
        TP.t[1]  = { a_sw, aswT, CS, CA };
        TP.t[2]  = { aogw, aogwT, CS, CA };
        TP.t[3]  = { t_gw, tgwT, CS, CA };
        TP.t[4]  = { t_sw, tswT, CS, CA };
        TP.t[5]  = { togw, togwT, CS, CA };
        TP.t[6]  = { wq, wqT, CA, CA };
        TP.t[7]  = { wk, wkT, CA, CA };
        TP.t[8]  = { wv, wvT, CA, CA };
        TP.t[9]  = { wg, wgT, CA, CA };
        TP.t[10] = { wo, woT, CA, CA };
        TP.t[11] = { w1, w1T, CA, 1536 };
        TP.t[12] = { w2, w2T, CA, 1536 };
        TP.t[13] = { two, twoT, 1536, CA };
        trans_k<<<dim3(48, 48, 14), 256>>>(TP);
    }
    lns_k<<<NT, 128>>>(s, a_slng, t_slng);

    // ---- batch 1: six s-conditioned gate/skip GEMMs (K=384) -> fp32 ----
    {
        ZPack P;
        P.z[0] = mk(slnA, CS, agwT,  CS, gateA, CA, CA, CS, 1.f, 1, 1, a_gb);
        P.z[1] = mk(slnA, CS, aswT,  CS, skipA, CA, CA, CS, 1.f, 0, 0);
        P.z[2] = mk(sbf,  CS, aogwT, CS, outGA, CA, CA, CS, 1.f, 1, 1, aogb);
        P.z[3] = mk(slnT, CS, tgwT,  CS, gateT, CA, CA, CS, 1.f, 1, 1, t_gb);
        P.z[4] = mk(slnT, CS, tswT,  CS, skipT, CA, CA, CS, 1.f, 0, 0);
        P.z[5] = mk(sbf,  CS, togwT, CS, outGT, CA, CA, CS, 1.f, 1, 1, togb);
        bgemm_k<128,0><<<dim3(12,6,6), 256>>>(P);
    }

    adaln_k<<<NT, 256>>>(a, gateA, skipA, aln);

    // ---- batch 2: QKVG projections (K=768) -> bf16 ----
    {
        ZPack P;
        P.z[0] = mk(aln, CA, wqT, CA, qb, CA, CA, CA, 1.f, 0, 1, bq);
        P.z[1] = mk(aln, CA, wkT, CA, kb, CA, CA, CA, 1.f, 0, 0);
        P.z[2] = mk(aln, CA, wvT, CA, vT, NT, CA, CA, 1.f, 0, 32);
        P.z[3] = mk(aln, CA, wgT, CA, gb, CA, CA, CA, 1.f, 1, 0);
        bgemm_k<128,1><<<dim3(12,6,4), 256>>>(P);
    }

    pairbias_k<<<NN/(8*PPW), 256>>>(z, logits);

    // ---- batch 3: logits per head (K=48), fp32 out, bias+mask fused ----
    {
        ZPack P;
        for (int h = 0; h < NH; h++)
            P.z[h] = mk(qb + 48*h, CA, kb + 48*h, CA,
                        logits + (ll)NN*h, NT, NT, CH, 0.14433756729740643f,
                        0, 1 | 2, maskb, logits + (ll)NN*h, NT);
        bgemm_k<128,0><<<dim3(12,6,16), 256>>>(P);
    }

    softmax_k<<<NH*NT, 256>>>(logits, probs);

    // ---- batch 4: AV per head (K=768), gated by g -> bf16 og ----
    {
        ZPack P;
        for (int h = 0; h < NH; h++)
            P.z[h] = mk(probs + (ll)NN*h, NT, vT + (ll)48*NT*h, NT,
                        og + 48*h, CA, CH, NT, 1.f,
                        0, 64, nullptr, nullptr, 0, nullptr, gb + 48*h, CA);
        bgemm_k<64,1><<<dim3(1,12,16), 256>>>(P);
    }

    // ---- a_new = a + outGA * (og @ wo) -> fp32 ----
    {
        ZPack P;
        P.z[0] = mk(og, CA, woT, CA, anew, CA, CA, CA, 1.f,
                    0, 4 | 8, nullptr, nullptr, 0, outGA, nullptr, CA, a, CA);
        bgemm_k<64,0><<<dim3(12,12,1), 256>>>(P);
    }

    adaln_k<<<NT, 256>>>(anew, gateT, skipT, aln);

    // ---- SwiGLU (K=768, N=1536) ----
    {
        ZPack P;
        P.z[0] = mk(aln, CA, w1T, CA, h1, 1536, 1536, CA, 1.f, 2, 0);
        bgemm_k<128,1><<<dim3(24,6,1), 256>>>(P);
    }
    {
        ZPack P;
        P.z[0] = mk(aln, CA, w2T, CA, hid, 1536, 1536, CA, 1.f,
                    0, 64, nullptr, nullptr, 0, nullptr, h1, 1536);
        bgemm_k<128,1><<<dim3(24,6,1), 256>>>(P);
    }

    // ---- out = a_new + maskf * outGT * (hid @ tr_wo) -> fp32 ----
    {
        ZPack P;
        P.z[0] = mk(hid, 1536, twoT, 1536, out, CA, CA, 1536, 1.f,
                    0, 4 | 8 | 16, nullptr, nullptr, 0, outGT, nullptr, CA,
                    anew, CA, maskf);
        bgemm_k<64,0><<<dim3(12,12,1), 256>>>(P);
    }
}

// round 14
// speedup vs baseline: 2.3563x; 1.0295x over previous
#include <cuda_runtime.h>
#include <cuda_bf16.h>
#include <math.h>

typedef long long ll;
typedef unsigned long long ull;

#define NT 768
#define CA 768
#define CS 384
#define CZ 128
#define NH 16
#define CH 48
#define NN (768*768)

// ---------------- fp32 scratch ----------------
__device__ float g_gateA[NT*CA], g_skipA[NT*CA], g_outGA[NT*CA];
__device__ float g_gateT[NT*CA], g_skipT[NT*CA], g_outGT[NT*CA];
__device__ float g_logits[NH*NN];
__device__ float g_anew[NT*CA];
__device__ float g_Wp[NH*CZ], g_Sv[NH], g_Cv[NH], g_maskb[NT], g_maskf[NT];

// ---------------- bf16 scratch ----------------
__device__ __nv_bfloat16 b_slnA[NT*CS], b_slnT[NT*CS], b_s[NT*CS];
__device__ __nv_bfloat16 b_aln[NT*CA], b_q[NT*CA], b_k[NT*CA];
__device__ __nv_bfloat16 b_vT[CA*NT], b_g[NT*CA];
__device__ __nv_bfloat16 b_probs[NH*NN];
__device__ __nv_bfloat16 b_og[NT*CA], b_h1[NT*1536], b_hid[NT*1536];
__device__ __nv_bfloat16 b_wpool[8257536];

// ---------------- helpers ----------------
__device__ __forceinline__ ull pk2(float x, float y) {
    ull r; asm("mov.b64 %0, {%1, %2};" : "=l"(r) : "f"(x), "f"(y)); return r;
}
__device__ __forceinline__ void fma2(ull &d, ull a, ull b) {
    asm("fma.rn.f32x2 %0, %1, %2, %0;" : "+l"(d) : "l"(a), "l"(b));
}
__device__ __forceinline__ float sum2(ull v) {
    float x, y; asm("mov.b64 {%0, %1}, %2;" : "=f"(x), "=f"(y) : "l"(v));
    return x + y;
}
__device__ __forceinline__ unsigned su32(const void* p) {
    return (unsigned)__cvta_generic_to_shared(p);
}
__device__ __forceinline__ void cpa16(unsigned dst, const void* src, int bytes) {
    asm volatile("cp.async.ca.shared.global [%0], [%1], 16, %2;\n"
                 :: "r"(dst), "l"(src), "r"(bytes));
}
__device__ __forceinline__ void cpcommit() { asm volatile("cp.async.commit_group;\n"); }
template<int Ng> __device__ __forceinline__ void cpwait() {
    asm volatile("cp.async.wait_group %0;\n" :: "n"(Ng));
}
__device__ __forceinline__ void ldsm4(unsigned &r0, unsigned &r1, unsigned &r2,
                                      unsigned &r3, unsigned addr) {
    asm volatile("ldmatrix.sync.aligned.m8n8.x4.shared.b16 {%0,%1,%2,%3}, [%4];"
                 : "=r"(r0), "=r"(r1), "=r"(r2), "=r"(r3) : "r"(addr));
}

__device__ __forceinline__ float blkreduce(float v, bool domax) {
    __shared__ float sm[32];
    const unsigned F = 0xffffffffu;
    #pragma unroll
    for (int o = 16; o; o >>= 1) {
        float u = __shfl_xor_sync(F, v, o);
        v = domax ? fmaxf(v, u) : v + u;
    }
    __syncthreads();
    if ((threadIdx.x & 31) == 0) sm[threadIdx.x >> 5] = v;
    __syncthreads();
    int nw = blockDim.x >> 5;
    if (threadIdx.x < 32) {
        float u = (threadIdx.x < nw) ? sm[threadIdx.x] : (domax ? -3.4e38f : 0.f);
        #pragma unroll
        for (int o = 16; o; o >>= 1) {
            float w = __shfl_xor_sync(F, u, o);
            u = domax ? fmaxf(u, w) : u + w;
        }
        if (threadIdx.x == 0) sm[0] = u;
    }
    __syncthreads();
    return sm[0];
}

// ---------------- prep: mask, folded pair-bias weights ----------------
__global__ void prep_k(const int* __restrict__ mask, const float* __restrict__ zg,
                       const float* __restrict__ zb, const float* __restrict__ wb) {
    int t = threadIdx.x;
    for (int i = t; i < NT; i += 256) {
        float m = (float)mask[i];
        g_maskf[i] = m;
        g_maskb[i] = (m - 1.f) * 1e9f;
    }
    for (int i = t; i < NH*CZ; i += 256) {
        int h = i >> 7, c = i & 127;
        g_Wp[i] = zg[c] * wb[c*NH + h];
    }
    if (t < NH) {
        float s = 0.f, cs = 0.f;
        for (int c = 0; c < CZ; c++) {
            s  += zg[c] * wb[c*NH + t];
            cs += zb[c] * wb[c*NH + t];
        }
        g_Sv[t] = s; g_Cv[t] = cs;
    }
}

// ---------------- weight transpose + bf16 convert ----------------
struct TArg { const float* src; __nv_bfloat16* dst; int K; int N; };
struct TPack { TArg t[14]; };

__global__ __launch_bounds__(256) void trans_k(TPack P) {
    TArg ta = P.t[blockIdx.z];
    int x0 = blockIdx.x * 32, y0 = blockIdx.y * 32;
    if (x0 >= ta.N || y0 >= ta.K) return;
    __shared__ float tile[32][33];
    int tx = threadIdx.x & 31, ty = threadIdx.x >> 5;  // 32x8
    #pragma unroll
    for (int i = 0; i < 32; i += 8) {
        int k = y0 + ty + i, n = x0 + tx;
        if (k < ta.K && n < ta.N) tile[ty + i][tx] = ta.src[(ll)k * ta.N + n];
    }
    __syncthreads();
    #pragma unroll
    for (int i = 0; i < 32; i += 8) {
        int n = x0 + ty + i, k = y0 + tx;
        if (n < ta.N && k < ta.K)
            ta.dst[(ll)n * ta.K + k] = __float2bfloat16_rn(tile[tx][ty + i]);
    }
}

// ---------------- LN(s) dual scale + bf16 s copy ----------------
__global__ __launch_bounds__(128) void lns_k(const float* __restrict__ s,
                                             const float* __restrict__ gA,
                                             const float* __restrict__ gT) {
    int r = blockIdx.x, t = threadIdx.x;
    const float* x = s + (ll)r * CS;
    float v[3]; float su = 0.f, q = 0.f;
    #pragma unroll
    for (int i = 0; i < 3; i++) { v[i] = x[t + 128*i]; su += v[i]; q += v[i]*v[i]; }
    su = blkreduce(su, false);
    q  = blkreduce(q, false);
    float mu = su * (1.f/CS);
    float rs = rsqrtf(q * (1.f/CS) - mu*mu + 1e-5f);
    ll base = (ll)r * CS;
    #pragma unroll
    for (int i = 0; i < 3; i++) {
        int c = t + 128*i;
        float xh = (v[i] - mu) * rs;
        b_slnA[base + c] = __float2bfloat16_rn(xh * gA[c]);
        b_slnT[base + c] = __float2bfloat16_rn(xh * gT[c]);
        b_s[base + c]    = __float2bfloat16_rn(v[i]);
    }
}

// ---------------- AdaLN combine -> bf16 ----------------
__global__ __launch_bounds__(256) void adaln_k(const float* __restrict__ a,
                                               const float* __restrict__ gate,
                                               const float* __restrict__ skip,
                                               __nv_bfloat16* __restrict__ out) {
    int r = blockIdx.x, t = threadIdx.x;
    const float* x = a + (ll)r * CA;
    float v[3]; float su = 0.f, q = 0.f;
    #pragma unroll
    for (int i = 0; i < 3; i++) { v[i] = x[t + 256*i]; su += v[i]; q += v[i]*v[i]; }
    su = blkreduce(su, false);
    q  = blkreduce(q, false);
    float mu = su * (1.f/CA);
    float rs = rsqrtf(q * (1.f/CA) - mu*mu + 1e-5f);
    ll base = (ll)r * CA;
    #pragma unroll
    for (int i = 0; i < 3; i++) {
        int c = t + 256*i;
        out[base + c] = __float2bfloat16_rn(
            gate[base + c] * ((v[i] - mu) * rs) + skip[base + c]);
    }
}

// ---------------- pair bias ----------------
#define PPW 16
__global__ __launch_bounds__(256) void pairbias_k(const float* __restrict__ z,
                                                  float* __restrict__ out) {
    __shared__ float stage[8][PPW][17];
    int t = threadIdx.x, w = t >> 5, l = t & 31;
    int h = l & 15, half = l >> 4;
    const unsigned F = 0xffffffffu;

    ull wreg[32];
    {
        const float4* wrow = (const float4*)(&g_Wp[h*CZ + half*64]);
        #pragma unroll
        for (int j = 0; j < 16; j++) {
            float4 wv = wrow[j];
            wreg[2*j]   = pk2(wv.x, wv.y);
            wreg[2*j+1] = pk2(wv.z, wv.w);
        }
    }
    float Svr = g_Sv[h], Cvr = g_Cv[h];
    ll pbase = ((ll)blockIdx.x * 8 + w) * PPW;

    for (int pi = 0; pi < PPW; pi++) {
        ll p = pbase + pi;
        const float4* zr = (const float4*)(z + p * CZ);
        float4 zc = zr[l];
        float su = zc.x + zc.y + zc.z + zc.w;
        float sq = zc.x*zc.x + zc.y*zc.y + zc.z*zc.z + zc.w*zc.w;
        ull acc = 0;
        const float4* zh = zr + half * 16;
        #pragma unroll
        for (int j = 0; j < 16; j++) {
            float4 zv = zh[j];
            fma2(acc, pk2(zv.x, zv.y), wreg[2*j]);
            fma2(acc, pk2(zv.z, zv.w), wreg[2*j+1]);
        }
        #pragma unroll
        for (int o = 16; o; o >>= 1) {
            su += __shfl_xor_sync(F, su, o);
            sq += __shfl_xor_sync(F, sq, o);
        }
        float dsum = sum2(acc);
        float dfull = dsum + __shfl_xor_sync(F, dsum, 16);
        float mu = su * (1.f/CZ);
        float rs = rsqrtf(sq * (1.f/CZ) - mu*mu + 1e-5f);
        if (l < 16)
            stage[w][pi][l] = rs * (dfull - mu * Svr) + Cvr;
    }
    __syncwarp();
    #pragma unroll
    for (int hh = 0; hh < NH; hh++) {
        if (l < PPW)
            out[(ll)hh * NN + pbase + l] = stage[w][l][hh];
    }
}

// ---------------- softmax: fp32 logits -> bf16 probs ----------------
__global__ __launch_bounds__(256) void softmax_k(const float* __restrict__ lg,
                                                 __nv_bfloat16* __restrict__ pr) {
    ll base = (ll)blockIdx.x * NT;
    int t = threadIdx.x;
    float v0 = lg[base+t], v1 = lg[base+t+256], v2 = lg[base+t+512];
    float mx = blkreduce(fmaxf(v0, fmaxf(v1, v2)), true);
    float e0 = __expf(v0 - mx), e1 = __expf(v1 - mx), e2 = __expf(v2 - mx);
    float s = blkreduce(e0 + e1 + e2, false);
    float inv = 1.f / s;
    pr[base+t]     = __float2bfloat16_rn(e0*inv);
    pr[base+t+256] = __float2bfloat16_rn(e1*inv);
    pr[base+t+512] = __float2bfloat16_rn(e2*inv);
}

// ---------------- batched bf16 MMA GEMM, 32-wide stages, 3-stage cp.async ----------------
// flags: 1=BVEC 2=MATB(f32) 4=MULF32 8=ADDF32 16=ROWSC 32=STORET 64=MULBF16
struct ZArg {
    const __nv_bfloat16 *A, *W, *mulb;
    const float *bvec, *matb, *mulf, *addm, *rowsc;
    void *C;
    int lda, ldw, ldc, ldmb, ldmul, ldadd;
    int actf; float scale; int N, K;
};
struct ZPack { ZArg z[16]; };

template<int BMv, int OUTBF>
__global__ __launch_bounds__(256) void bgemm_k(ZPack P) {
    const ZArg za = P.z[blockIdx.z];
    // 40-element (80B) padded rows: 16B-aligned, ldmatrix conflict-free (r*5 mod 8)
    __shared__ __align__(16) __nv_bfloat16 As[3][BMv][40];
    __shared__ __align__(16) __nv_bfloat16 Bs[3][64][40];
    constexpr unsigned ASTG = BMv * 40u * 2u;
    constexpr unsigned BSTG = 64 * 40u * 2u;
    int t = threadIdx.x;
    int m0 = blockIdx.y * BMv, n0 = blockIdx.x * 64;
    const int K = za.K, N = za.N;
    int niter = (K + 31) >> 5;
    int nrem = N - n0;

    // hoisted load addressing: 4 threads per row, 8-elem (16B) chunks
    int lrow = t >> 2, lkc = (t & 3) * 8;
    const __nv_bfloat16* aSrc0 = za.A + (ll)(m0 + lrow) * za.lda + lkc;
    const __nv_bfloat16* aSrc1 = (BMv == 128) ?
        za.A + (ll)(m0 + lrow + 64) * za.lda + lkc : nullptr;
    const __nv_bfloat16* bSrc  = za.W + (ll)(n0 + lrow) * za.ldw + lkc;
    bool brOK = lrow < nrem;
    unsigned dA0 = su32(&As[0][lrow][lkc]);
    unsigned dA1 = (BMv == 128) ? su32(&As[0][lrow + 64][lkc]) : 0u;
    unsigned dB  = su32(&Bs[0][lrow][lkc]);

    auto load_stage = [&](int st, int k0) {
        int rem = (K - k0 - lkc) * 2;
        int kb = rem >= 16 ? 16 : (rem > 0 ? rem : 0);
        unsigned oA = st * ASTG, oB = st * BSTG;
        cpa16(dA0 + oA, kb ? aSrc0 + k0 : za.A, kb);
        if (BMv == 128) cpa16(dA1 + oA, kb ? aSrc1 + k0 : za.A, kb);
        int bb = brOK ? kb : 0;
        cpa16(dB + oB, bb ? bSrc + k0 : za.W, bb);
    };

    #pragma unroll
    for (int i = 0; i < 2; i++) {
        if (i < niter) load_stage(i, i * 32);
        cpcommit();
    }

    int wid = t >> 5, lane = t & 31;
    int lr = lane >> 2, lc = lane & 3;
    constexpr int NTW = (BMv == 128) ? 4 : 2;
    int wm = (BMv == 128) ? (wid & 3) * 32 : (wid & 1) * 32;
    int wn = (BMv == 128) ? (wid >> 2) * 32 : (wid >> 1) * 16;

    unsigned aAddr, bAddr;
    {
        int arow = wm + (lane & 15);
        int acol = (lane >> 4) * 8;
        aAddr = su32(&As[0][0][0]) + (unsigned)(arow * 40 + acol) * 2;
        int brow = wn + ((lane >> 4) * 8) + (lane & 7);
        int bcol = ((lane >> 3) & 1) * 8;
        bAddr = su32(&Bs[0][0][0]) + (unsigned)(brow * 40 + bcol) * 2;
    }

    float acc[2][NTW][4] = {};

    int st = 0;
    for (int it = 0; it < niter; it++) {
        cpwait<1>();
        __syncthreads();
        int pf = it + 2;
        if (pf < niter) {
            int pst = st + 2; if (pst >= 3) pst -= 3;
            load_stage(pst, pf * 32);
        }
        cpcommit();
        unsigned sA = aAddr + st * ASTG;
        unsigned sB = bAddr + st * BSTG;

        #pragma unroll
        for (int ksb = 0; ksb < 64; ksb += 32) {  // two k16 chunks (bytes)
            unsigned afr[2][4], bfr[NTW][2];
            #pragma unroll
            for (int mt = 0; mt < 2; mt++)
                ldsm4(afr[mt][0], afr[mt][1], afr[mt][2], afr[mt][3],
                      sA + ksb + mt * 1280u);
            #pragma unroll
            for (int np = 0; np < NTW/2; np++)
                ldsm4(bfr[2*np][0], bfr[2*np][1], bfr[2*np+1][0], bfr[2*np+1][1],
                      sB + ksb + np * 1280u);
            #pragma unroll
            for (int mt = 0; mt < 2; mt++)
                #pragma unroll
                for (int nt = 0; nt < NTW; nt++) {
                    float* cc = acc[mt][nt];
                    asm volatile(
                        "mma.sync.aligned.m16n8k16.row.col.f32.bf16.bf16.f32 "
                        "{%0,%1,%2,%3}, {%4,%5,%6,%7}, {%8,%9}, {%0,%1,%2,%3};\n"
                        : "+f"(cc[0]), "+f"(cc[1]), "+f"(cc[2]), "+f"(cc[3])
                        : "r"(afr[mt][0]), "r"(afr[mt][1]), "r"(afr[mt][2]), "r"(afr[mt][3]),
                          "r"(bfr[nt][0]), "r"(bfr[nt][1]));
                }
        }
        if (++st == 3) st = 0;
    }

    int act = za.actf & 15, flg = za.actf >> 4;
    auto ep = [&](int m, int n, float v) {
        if (n >= N) return;
        v *= za.scale;
        if (flg & 1)  v += za.bvec[n];
        if (flg & 2)  v += za.matb[(ll)m * za.ldmb + n];
        if (act == 1) v = 1.f / (1.f + __expf(-v));
        else if (act == 2) v = v / (1.f + __expf(-v));
        if (flg & 4)  v *= za.mulf[(ll)m * za.ldmul + n];
        if (flg & 64) v *= __bfloat162float(za.mulb[(ll)m * za.ldmul + n]);
        if (flg & 16) v *= za.rowsc[m];
        if (flg & 8)  v += za.addm[(ll)m * za.ldadd + n];
        ll idx = (flg & 32) ? (ll)n * za.ldc + m : (ll)m * za.ldc + n;
        if (OUTBF) ((__nv_bfloat16*)za.C)[idx] = __float2bfloat16_rn(v);
        else       ((float*)za.C)[idx] = v;
    };
    #pragma unroll
    for (int mt = 0; mt < 2; mt++)
        #pragma unroll
        for (int nt = 0; nt < NTW; nt++) {
            int mrow = m0 + wm + 16*mt + lr;
            int ncol = n0 + wn + 8*nt + 2*lc;
            float* cc = acc[mt][nt];
            ep(mrow,     ncol,     cc[0]);
            ep(mrow,     ncol + 1, cc[1]);
            ep(mrow + 8, ncol,     cc[2]);
            ep(mrow + 8, ncol + 1, cc[3]);
        }
}

// ---------------- host orchestration ----------------
#define SYM(p, ty, name) do { void* _t; cudaGetSymbolAddress(&_t, name); p = (ty*)_t; } while (0)

static ZArg mk(const __nv_bfloat16* A, int lda, const __nv_bfloat16* W, int ldw,
               void* C, int ldc, int N, int K, float scale, int act, int flg,
               const float* bvec = nullptr,
               const float* matb = nullptr, int ldmb = 0,
               const float* mulf = nullptr, const __nv_bfloat16* mulb = nullptr, int ldmul = 0,
               const float* addm = nullptr, int ldadd = 0,
               const float* rowsc = nullptr) {
    ZArg z;
    z.A = A; z.W = W; z.C = C; z.bvec = bvec; z.matb = matb;
    z.mulf = mulf; z.mulb = mulb; z.addm = addm; z.rowsc = rowsc;
    z.lda = lda; z.ldw = ldw; z.ldc = ldc; z.ldmb = ldmb; z.ldmul = ldmul; z.ldadd = ldadd;
    z.actf = act | (flg << 4); z.scale = scale; z.N = N; z.K = K;
    return z;
}

extern "C" void kernel_launch(void* const* d_in, const int* in_sizes, int n_in,
                              void* d_out, int out_size) {
    const float* a    = (const float*)d_in[0];
    const float* s    = (const float*)d_in[1];
    const float* z    = (const float*)d_in[2];
    const int*   mask = (const int*)  d_in[3];
    const float* a_slng  = (const float*)d_in[4];
    const float* a_gw    = (const float*)d_in[5];
    const float* a_gb    = (const float*)d_in[6];
    const float* a_sw    = (const float*)d_in[7];
    const float* wq   = (const float*)d_in[8];
    const float* bq   = (const float*)d_in[9];
    const float* wk   = (const float*)d_in[10];
    const float* wv   = (const float*)d_in[11];
    const float* zlng = (const float*)d_in[12];
    const float* zlnb = (const float*)d_in[13];
    const float* wb   = (const float*)d_in[14];
    const float* wg   = (const float*)d_in[15];
    const float* wo   = (const float*)d_in[16];
    const float* aogw = (const float*)d_in[17];
    const float* aogb = (const float*)d_in[18];
    const float* t_slng = (const float*)d_in[19];
    const float* t_gw   = (const float*)d_in[20];
    const float* t_gb   = (const float*)d_in[21];
    const float* t_sw   = (const float*)d_in[22];
    const float* w1   = (const float*)d_in[23];
    const float* w2   = (const float*)d_in[24];
    const float* two  = (const float*)d_in[25];
    const float* togw = (const float*)d_in[26];
    const float* togb = (const float*)d_in[27];
    float* out = (float*)d_out;

    float *gateA,*skipA,*outGA,*gateT,*skipT,*outGT,*logits,*anew,*maskb,*maskf;
    SYM(gateA, float, g_gateA); SYM(skipA, float, g_skipA); SYM(outGA, float, g_outGA);
    SYM(gateT, float, g_gateT); SYM(skipT, float, g_skipT); SYM(outGT, float, g_outGT);
    SYM(logits, float, g_logits); SYM(anew, float, g_anew);
    SYM(maskb, float, g_maskb); SYM(maskf, float, g_maskf);

    __nv_bfloat16 *slnA,*slnT,*sbf,*aln,*qb,*kb,*vT,*gb,*probs,*og,*h1,*hid,*wpool;
    SYM(slnA, __nv_bfloat16, b_slnA); SYM(slnT, __nv_bfloat16, b_slnT);
    SYM(sbf, __nv_bfloat16, b_s);     SYM(aln, __nv_bfloat16, b_aln);
    SYM(qb, __nv_bfloat16, b_q);      SYM(kb, __nv_bfloat16, b_k);
    SYM(vT, __nv_bfloat16, b_vT);     SYM(gb, __nv_bfloat16, b_g);
    SYM(probs, __nv_bfloat16, b_probs); SYM(og, __nv_bfloat16, b_og);
    SYM(h1, __nv_bfloat16, b_h1);     SYM(hid, __nv_bfloat16, b_hid);
    SYM(wpool, __nv_bfloat16, b_wpool);

    // weight pool offsets
    const ll GSZ = (ll)CS*CA, PSZ = (ll)CA*CA, WSZ = (ll)CA*1536;
    __nv_bfloat16 *agwT = wpool,        *aswT = agwT + GSZ, *aogwT = aswT + GSZ;
    __nv_bfloat16 *tgwT = aogwT + GSZ,  *tswT = tgwT + GSZ, *togwT = tswT + GSZ;
    __nv_bfloat16 *wqT = togwT + GSZ, *wkT = wqT + PSZ, *wvT = wkT + PSZ;
    __nv_bfloat16 *wgT = wvT + PSZ, *woT = wgT + PSZ;
    __nv_bfloat16 *w1T = woT + PSZ, *w2T = w1T + WSZ, *twoT = w2T + WSZ;

    prep_k<<<1, 256>>>(mask, zlng, zlnb, wb);
    {
        TPack TP;
        TP.t[0]  = { a_gw, agwT, CS, CA };
        TP.t[1]  = { a_sw, aswT, CS, CA };
        TP.t[2]  = { aogw, aogwT, CS, CA };
        TP.t[3]  = { t_gw, tgwT, CS, CA };
        TP.t[4]  = { t_sw, tswT, CS, CA };
        TP.t[5]  = { togw, togwT, CS, CA };
        TP.t[6]  = { wq, wqT, CA, CA };
        TP.t[7]  = { wk, wkT, CA, CA };
        TP.t[8]  = { wv, wvT, CA, CA };
        TP.t[9]  = { wg, wgT, CA, CA };
        TP.t[10] = { wo, woT, CA, CA };
        TP.t[11] = { w1, w1T, CA, 1536 };
        TP.t[12] = { w2, w2T, CA, 1536 };
        TP.t[13] = { two, twoT, 1536, CA };
        trans_k<<<dim3(48, 48, 14), 256>>>(TP);
    }
    lns_k<<<NT, 128>>>(s, a_slng, t_slng);

    // ---- batch 1: six s-conditioned gate/skip GEMMs (K=384) -> fp32 ----
    {
        ZPack P;
        P.z[0] = mk(slnA, CS, agwT,  CS, gateA, CA, CA, CS, 1.f, 1, 1, a_gb);
        P.z[1] = mk(slnA, CS, aswT,  CS, skipA, CA, CA, CS, 1.f, 0, 0);
        P.z[2] = mk(sbf,  CS, aogwT, CS, outGA, CA, CA, CS, 1.f, 1, 1, aogb);
        P.z[3] = mk(slnT, CS, tgwT,  CS, gateT, CA, CA, CS, 1.f, 1, 1, t_gb);
        P.z[4] = mk(slnT, CS, tswT,  CS, skipT, CA, CA, CS, 1.f, 0, 0);
        P.z[5] = mk(sbf,  CS, togwT, CS, outGT, CA, CA, CS, 1.f, 1, 1, togb);
        bgemm_k<128,0><<<dim3(12,6,6), 256>>>(P);
    }

    adaln_k<<<NT, 256>>>(a, gateA, skipA, aln);

    // ---- batch 2: QKVG projections (K=768) -> bf16 ----
    {
        ZPack P;
        P.z[0] = mk(aln, CA, wqT, CA, qb, CA, CA, CA, 1.f, 0, 1, bq);
        P.z[1] = mk(aln, CA, wkT, CA, kb, CA, CA, CA, 1.f, 0, 0);
        P.z[2] = mk(aln, CA, wvT, CA, vT, NT, CA, CA, 1.f, 0, 32);
        P.z[3] = mk(aln, CA, wgT, CA, gb, CA, CA, CA, 1.f, 1, 0);
        bgemm_k<128,1><<<dim3(12,6,4), 256>>>(P);
    }

    pairbias_k<<<NN/(8*PPW), 256>>>(z, logits);

    // ---- batch 3: logits per head (K=48), fp32 out, bias+mask fused ----
    {
        ZPack P;
        for (int h = 0; h < NH; h++)
            P.z[h] = mk(qb + 48*h, CA, kb + 48*h, CA,
                        logits + (ll)NN*h, NT, NT, CH, 0.14433756729740643f,
                        0, 1 | 2, maskb, logits + (ll)NN*h, NT);
        bgemm_k<128,0><<<dim3(12,6,16), 256>>>(P);
    }

    softmax_k<<<NH*NT, 256>>>(logits, probs);

    // ---- batch 4: AV per head (K=768), gated by g -> bf16 og ----
    {
        ZPack P;
        for (int h = 0; h < NH; h++)
            P.z[h] = mk(probs + (ll)NN*h, NT, vT + (ll)48*NT*h, NT,
                        og + 48*h, CA, CH, NT, 1.f,
                        0, 64, nullptr, nullptr, 0, nullptr, gb + 48*h, CA);
        bgemm_k<64,1><<<dim3(1,12,16), 256>>>(P);
    }

    // ---- a_new = a + outGA * (og @ wo) -> fp32 ----
    {
        ZPack P;
        P.z[0] = mk(og, CA, woT, CA, anew, CA, CA, CA, 1.f,
                    0, 4 | 8, nullptr, nullptr, 0, outGA, nullptr, CA, a, CA);
        bgemm_k<64,0><<<dim3(12,12,1), 256>>>(P);
    }

    adaln_k<<<NT, 256>>>(anew, gateT, skipT, aln);

    // ---- SwiGLU (K=768, N=1536) ----
    {
        ZPack P;
        P.z[0] = mk(aln, CA, w1T, CA, h1, 1536, 1536, CA, 1.f, 2, 0);
        bgemm_k<128,1><<<dim3(24,6,1), 256>>>(P);
    }
    {
        ZPack P;
        P.z[0] = mk(aln, CA, w2T, CA, hid, 1536, 1536, CA, 1.f,
                    0, 64, nullptr, nullptr, 0, nullptr, h1, 1536);
        bgemm_k<128,1><<<dim3(24,6,1), 256>>>(P);
    }

    // ---- out = a_new + maskf * outGT * (hid @ tr_wo) -> fp32 ----
    {
        ZPack P;
        P.z[0] = mk(hid, 1536, twoT, 1536, out, CA, CA, 1536, 1.f,
                    0, 4 | 8 | 16, nullptr, nullptr, 0, outGT, nullptr, CA,
                    anew, CA, maskf);
        bgemm_k<64,0><<<dim3(12,12,1), 256>>>(P);
    }
}